// round 3
// baseline (speedup 1.0000x reference)
#include <cuda_runtime.h>
#include <math.h>

#define V 307
#define T 12
#define E 32
#define B 128
#define NPRE 12
#define TE 384      // T*E
#define N2 768      // 2E*T
#define VE2 19648   // V*2E
#define VV 94249    // V*V
#define BT 1536     // B*T
#define IN_ROW 309
#define IN_B 4017   // 13*309
#define HB 235776   // V*N2 = 12*VE2  (per-batch h3 elements)
#define KSPLIT 8
#define KCH 2456    // VE2 / KSPLIT

// ---------------- scratch (static device globals; no cudaMalloc allowed) ----
__device__ float g_rpe[VV];
__device__ float g_rpeT[VV];
__device__ float g_rel[VV];
__device__ float g_rsum[V];
__device__ float g_x3d[BT * V];    // x3 dense [bt][v]
__device__ float g_y[BT * V];      // y = X3 @ rel
__device__ float g_hA[B * V * TE]; // connect output, layout [b][g][t*E+e]
__device__ float g_h3[B * HB];     // dyn output, layout [b][t][g][i]  (i in 2E)
__device__ float g_tgp[KSPLIT * BT * V]; // split-K partials for tg
__device__ float g_tg[BT * V];     // tg[bt][v]
__device__ float g_gt[B * V * NPRE]; // gt[b*V+g][o]  (o = T = 12)

__device__ __forceinline__ float leakyf(float x) { return x >= 0.f ? x : 0.3f * x; }

// ---------------- K0a: gather rpe + transpose -------------------------------
__global__ void k_gather(const float* __restrict__ srpe, const int* __restrict__ sdist) {
    int i = blockIdx.x * 256 + threadIdx.x;
    if (i < VV) {
        float v = srpe[sdist[i]];
        g_rpe[i] = v;
        g_rpeT[(i % V) * V + (i / V)] = v;
    }
}

// ---------------- K0b: rel = relu(rpe @ rpe^T), rowsum ----------------------
__global__ void k_rel() {
    __shared__ float s[V];
    __shared__ float red[256];
    int v = blockIdx.x;
    for (int k = threadIdx.x; k < V; k += 256) s[k] = g_rpe[v * V + k];
    __syncthreads();
    float lr = 0.f;
    for (int g = threadIdx.x; g < V; g += 256) {
        float sum = 0.f;
        for (int k = 0; k < V; k++) sum += s[k] * g_rpeT[k * V + g];
        float r = sum > 0.f ? sum : 0.f;
        g_rel[v * V + g] = r;
        lr += r;
    }
    red[threadIdx.x] = lr;
    __syncthreads();
    for (int st = 128; st > 0; st >>= 1) {
        if (threadIdx.x < st) red[threadIdx.x] += red[threadIdx.x + st];
        __syncthreads();
    }
    if (threadIdx.x == 0) g_rsum[v] = red[0];
}

// ---------------- K1x: extract dense x3 [bt][v] -----------------------------
__global__ void k_x3(const float* __restrict__ inp) {
    int idx = blockIdx.x * 256 + threadIdx.x;
    if (idx >= BT * V) return;
    int bt = idx / V, v = idx % V;
    int b = bt / T, t = bt % T;
    g_x3d[idx] = inp[b * IN_B + (1 + t) * IN_ROW + 2 + v];
}

// ---------------- shared SGEMM tile core (64x64, BK=16, 256 thr, 4x4/thr) ---
__device__ __forceinline__ void gemm_tile(
    const float* __restrict__ A, int lda, int M,
    const float* __restrict__ Bm, int ldb, int N,
    int m0, int n0, int kbeg, int kend, float acc[4][4])
{
    __shared__ float sA[16 * 64];
    __shared__ float sB[16 * 64];
    int tid = threadIdx.x;
    int tm = (tid >> 4) << 2;
    int tn = (tid & 15) << 2;
    for (int k0 = kbeg; k0 < kend; k0 += 16) {
        #pragma unroll
        for (int i = 0; i < 4; i++) {
            int idx = tid + i * 256;
            int m = idx >> 4;
            int kk = idx & 15;
            int gm = m0 + m, gk = k0 + kk;
            float v = (gm < M && gk < kend) ? A[(size_t)gm * lda + gk] : 0.f;
            sA[kk * 64 + m] = v;
        }
        #pragma unroll
        for (int i = 0; i < 4; i++) {
            int idx = tid + i * 256;
            int kk = idx >> 6;
            int n = idx & 63;
            int gk = k0 + kk, gn = n0 + n;
            float v = (gk < kend && gn < N) ? Bm[(size_t)gk * ldb + gn] : 0.f;
            sB[kk * 64 + n] = v;
        }
        __syncthreads();
        #pragma unroll
        for (int kk = 0; kk < 16; kk++) {
            float4 a4 = *(const float4*)(sA + kk * 64 + tm);
            float4 b4 = *(const float4*)(sB + kk * 64 + tn);
            float av[4] = {a4.x, a4.y, a4.z, a4.w};
            float bv[4] = {b4.x, b4.y, b4.z, b4.w};
            #pragma unroll
            for (int x = 0; x < 4; x++)
                #pragma unroll
                for (int y = 0; y < 4; y++)
                    acc[x][y] += av[x] * bv[y];
        }
        __syncthreads();
    }
}

// ---------------- K1: y = X3 (1536x307) @ rel (307x307) ---------------------
__global__ void k_sgemm_y() {
    float acc[4][4] = {};
    int m0 = blockIdx.y * 64, n0 = blockIdx.x * 64;
    gemm_tile(g_x3d, V, BT, g_rel, V, V, m0, n0, 0, V, acc);
    int tid = threadIdx.x;
    int tm = (tid >> 4) << 2, tn = (tid & 15) << 2;
    #pragma unroll
    for (int x = 0; x < 4; x++) {
        int m = m0 + tm + x;
        if (m >= BT) continue;
        #pragma unroll
        for (int y = 0; y < 4; y++) {
            int n = n0 + tn + y;
            if (n < V) g_y[m * V + n] = acc[x][y];
        }
    }
}

// ---------------- K2: connect layer (per (v,t): 128x96 @ 96x32) -------------
__global__ void __launch_bounds__(128) k_connect(
    const float* __restrict__ inp,
    const float* __restrict__ conv_w, const float* __restrict__ conv_b,
    const float* __restrict__ sape, const float* __restrict__ dow,
    const float* __restrict__ tod,
    const float* __restrict__ cw, const float* __restrict__ cb)
{
    int v = blockIdx.x, t = blockIdx.y;
    __shared__ float s_cw[96 * 32];
    __shared__ float s_cb[32], s_w[32], s_b[32];
    const float* cwp = cw + (size_t)(t * V + v) * 96 * 32;
    for (int i = threadIdx.x; i < 3072; i += 128) s_cw[i] = cwp[i];
    if (threadIdx.x < 32) {
        s_cb[threadIdx.x] = cb[(t * V + v) * 32 + threadIdx.x];
        s_w[threadIdx.x] = conv_w[threadIdx.x];
        s_b[threadIdx.x] = conv_b[threadIdx.x];
    }
    __syncthreads();
    int b = threadIdx.x;
    float yv = g_y[(b * T + t) * V + v];
    float rv = g_rsum[v];
    int nr = (int)inp[b * IN_B + 2 + v];
    int sw = (int)inp[b * IN_B + (1 + t) * IN_ROW + 0];
    int sd = (int)inp[b * IN_B + (1 + t) * IN_ROW + 1];
    const float* sp = sape + (nr * T + t) * E;
    const float* dwp = dow + (sw * V + v) * E;
    const float* tdp = tod + (sd * V + v) * E;

    float acc[32];
    #pragma unroll
    for (int e = 0; e < 32; e++) acc[e] = s_cb[e];

    // segment 0: x_rel part
    #pragma unroll
    for (int f = 0; f < 32; f++) {
        float xf = yv * s_w[f] + rv * s_b[f];
        const float4* c4 = (const float4*)(s_cw + f * 32);
        #pragma unroll
        for (int e4 = 0; e4 < 8; e4++) {
            float4 w4 = c4[e4];
            acc[e4 * 4 + 0] += xf * w4.x; acc[e4 * 4 + 1] += xf * w4.y;
            acc[e4 * 4 + 2] += xf * w4.z; acc[e4 * 4 + 3] += xf * w4.w;
        }
    }
    // segment 1: pos (sape)
    #pragma unroll
    for (int f = 0; f < 32; f++) {
        float xf = sp[f];
        const float4* c4 = (const float4*)(s_cw + (32 + f) * 32);
        #pragma unroll
        for (int e4 = 0; e4 < 8; e4++) {
            float4 w4 = c4[e4];
            acc[e4 * 4 + 0] += xf * w4.x; acc[e4 * 4 + 1] += xf * w4.y;
            acc[e4 * 4 + 2] += xf * w4.z; acc[e4 * 4 + 3] += xf * w4.w;
        }
    }
    // segment 2: time emb
    #pragma unroll
    for (int f = 0; f < 32; f++) {
        float xf = dwp[f] + tdp[f];
        const float4* c4 = (const float4*)(s_cw + (64 + f) * 32);
        #pragma unroll
        for (int e4 = 0; e4 < 8; e4++) {
            float4 w4 = c4[e4];
            acc[e4 * 4 + 0] += xf * w4.x; acc[e4 * 4 + 1] += xf * w4.y;
            acc[e4 * 4 + 2] += xf * w4.z; acc[e4 * 4 + 3] += xf * w4.w;
        }
    }
    float* o = g_hA + (size_t)(b * V + v) * TE + t * E;
    #pragma unroll
    for (int e = 0; e < 32; e++) o[e] = leakyf(acc[e]);
}

// ---------------- K3: dynamic layer, per b: A(307x384)@(W1+W2)(384x768) -----
__global__ void k_dyn(const float* __restrict__ inp,
                      const float* __restrict__ w1all, const float* __restrict__ w2all,
                      const float* __restrict__ o1all, const float* __restrict__ o2all)
{
    int b = blockIdx.z;
    int wk = (int)inp[b * IN_B + 0];
    int dt = (int)inp[b * IN_B + 1];
    int m0 = blockIdx.y * 64, n0 = blockIdx.x * 64;
    float acc[4][4] = {};
    const float* A = g_hA + (size_t)b * V * TE;
    gemm_tile(A, TE, V, w1all + (size_t)wk * TE * N2, N2, N2, m0, n0, 0, TE, acc);
    gemm_tile(A, TE, V, w2all + (size_t)dt * TE * N2, N2, N2, m0, n0, 0, TE, acc);

    int tid = threadIdx.x;
    int tm = (tid >> 4) << 2, tn = (tid & 15) << 2;
    const float* b1 = o1all + (size_t)wk * HB;
    const float* b2 = o2all + (size_t)dt * HB;
    float* h3 = g_h3 + (size_t)b * HB;
    #pragma unroll
    for (int x = 0; x < 4; x++) {
        int g = m0 + tm + x;
        if (g >= V) continue;
        #pragma unroll
        for (int y = 0; y < 4; y++) {
            int n = n0 + tn + y;  // n = i*12 + j, n < 768 always
            float val = 0.5f * (acc[x][y] + b1[g * N2 + n] + b2[g * N2 + n]);
            val = leakyf(val);
            int i = n / 12, j = n % 12;
            h3[j * VE2 + g * 64 + i] = val;
        }
    }
}

// ---------------- K4: tg = H3(1536x19648) @ tge2tg(19648x307), split-K ------
__global__ void k_tg(const float* __restrict__ t2t) {
    int ks = blockIdx.z;
    int m0 = blockIdx.y * 64, n0 = blockIdx.x * 64;
    float acc[4][4] = {};
    gemm_tile(g_h3, VE2, BT, t2t, V, V, m0, n0, ks * KCH, (ks + 1) * KCH, acc);
    int tid = threadIdx.x;
    int tm = (tid >> 4) << 2, tn = (tid & 15) << 2;
    float* p = g_tgp + (size_t)ks * BT * V;
    #pragma unroll
    for (int x = 0; x < 4; x++) {
        int m = m0 + tm + x;
        #pragma unroll
        for (int y = 0; y < 4; y++) {
            int n = n0 + tn + y;
            if (n < V) p[m * V + n] = acc[x][y];
        }
    }
}

__global__ void k_tgr() {
    int i = blockIdx.x * 256 + threadIdx.x;
    if (i < BT * V) {
        float s = 0.f;
        #pragma unroll
        for (int k = 0; k < KSPLIT; k++) s += g_tgp[(size_t)k * BT * V + i];
        g_tg[i] = s;
    }
}

// ---------------- K5: gt = rows(H3 as (B*V)x768) @ gte2gt(768x12) -----------
__global__ void k_gt(const float* __restrict__ g2g) {
    __shared__ float s[N2 * NPRE]; // 9216 floats = 36KB
    for (int i = threadIdx.x; i < N2 * NPRE; i += 256) s[i] = g2g[i];
    __syncthreads();
    int wid = threadIdx.x >> 5, lane = threadIdx.x & 31;
    int r = blockIdx.x * 8 + wid;          // r < B*V = 39296 (grid exact)
    const float* row = g_h3 + (size_t)r * N2;
    float acc[NPRE] = {};
    for (int m = lane; m < N2; m += 32) {
        float a = row[m];
        const float* sm = s + m * NPRE;
        #pragma unroll
        for (int o = 0; o < NPRE; o++) acc[o] += a * sm[o];
    }
    #pragma unroll
    for (int o = 0; o < NPRE; o++) {
        #pragma unroll
        for (int st = 16; st > 0; st >>= 1)
            acc[o] += __shfl_xor_sync(0xffffffffu, acc[o], st);
    }
    if (lane == 0) {
        #pragma unroll
        for (int o = 0; o < NPRE; o++) g_gt[r * NPRE + o] = acc[o];
    }
}

// ---------------- K6: gates + weight1/2 + fully, write transposed out -------
__global__ void k_out(const float* __restrict__ w1, const float* __restrict__ w2,
                      const float* __restrict__ fw, const float* __restrict__ fb,
                      float* __restrict__ out)
{
    int idx = blockIdx.x * 256 + threadIdx.x;
    if (idx >= B * V) return;
    int b = idx / V, g = idx % V;
    float gt1[T], gt2[T];
    #pragma unroll
    for (int t = 0; t < T; t++) {
        float x3v = g_x3d[(b * T + t) * V + g];
        float tgv = g_tg[(b * T + t) * V + g];
        float gtv = g_gt[idx * NPRE + t];
        gt1[t] = (tgv + x3v) * (1.f / (1.f + expf(-tgv)));
        gt2[t] = (gtv + x3v) * (1.f / (1.f + expf(-gtv)));
    }
    float x1[NPRE], x2[NPRE];
    #pragma unroll
    for (int o = 0; o < NPRE; o++) { x1[o] = 0.f; x2[o] = 0.f; }
    #pragma unroll
    for (int i = 0; i < T; i++) {
        float a = gt1[i], c = gt2[i];
        #pragma unroll
        for (int o = 0; o < NPRE; o++) {
            x1[o] += w1[g * 144 + i * 12 + o] * a;
            x2[o] += w2[g * 144 + i * 12 + o] * c;
        }
    }
    #pragma unroll
    for (int o = 0; o < NPRE; o++) {
        float sacc = fb[o];
        #pragma unroll
        for (int i = 0; i < NPRE; i++) {
            sacc += x1[i] * fw[i * 12 + o] + x2[i] * fw[(12 + i) * 12 + o];
        }
        out[(size_t)b * NPRE * V + o * V + g] = sacc;
    }
}

// ---------------- launch -----------------------------------------------------
extern "C" void kernel_launch(void* const* d_in, const int* in_sizes, int n_in,
                              void* d_out, int out_size) {
    const float* inputs = (const float*)d_in[0];
    const int*   sdist  = (const int*)d_in[1];
    const float* conv_w = (const float*)d_in[2];
    const float* conv_b = (const float*)d_in[3];
    const float* srpe   = (const float*)d_in[4];
    const float* sape   = (const float*)d_in[5];
    const float* dow    = (const float*)d_in[6];
    const float* tod    = (const float*)d_in[7];
    const float* cw     = (const float*)d_in[8];
    const float* cb     = (const float*)d_in[9];
    const float* dw1    = (const float*)d_in[10];
    const float* do1    = (const float*)d_in[11];
    const float* dw2    = (const float*)d_in[12];
    const float* do2    = (const float*)d_in[13];
    const float* t2t    = (const float*)d_in[14];
    const float* g2g    = (const float*)d_in[15];
    const float* w1     = (const float*)d_in[16];
    const float* w2     = (const float*)d_in[17];
    const float* fw     = (const float*)d_in[18];
    const float* fb     = (const float*)d_in[19];
    float* out = (float*)d_out;

    k_gather<<<(VV + 255) / 256, 256>>>(srpe, sdist);
    k_rel<<<V, 256>>>();
    k_x3<<<(BT * V + 255) / 256, 256>>>(inputs);
    k_sgemm_y<<<dim3(5, 24), 256>>>();
    k_connect<<<dim3(V, T), 128>>>(inputs, conv_w, conv_b, sape, dow, tod, cw, cb);
    k_dyn<<<dim3(12, 5, B), 256>>>(inputs, dw1, dw2, do1, do2);
    k_tg<<<dim3(5, 24, KSPLIT), 256>>>(t2t);
    k_tgr<<<(BT * V + 255) / 256, 256>>>();
    k_gt<<<(B * V) / 8, 256>>>(g2g);
    k_out<<<(B * V + 255) / 256, 256>>>(w1, w2, fw, fb, out);
}

// round 5
// speedup vs baseline: 1.4290x; 1.4290x over previous
#include <cuda_runtime.h>
#include <math.h>

#define V 307
#define T 12
#define E 32
#define B 128
#define NPRE 12
#define TE 384      // T*E
#define N2 768      // 2E*T
#define VE2 19648   // V*2E
#define VV 94249    // V*V
#define BT 1536     // B*T
#define IN_ROW 309
#define IN_B 4017   // 13*309
#define HB 235776   // V*N2 = 12*VE2  (per-batch h3 elements)
#define KSPLIT 8
#define KCH 2456    // VE2 / KSPLIT

#define BM 128
#define BN 128
#define BKK 16

typedef unsigned long long ull;

// ---------------- scratch (static device globals; no cudaMalloc allowed) ----
__device__ float g_rpe[VV];
__device__ float g_rpeT[VV];
__device__ float g_rel[VV];
__device__ float g_rsum[V];
__device__ float g_x3d[BT * V];    // x3 dense [bt][v]
__device__ float g_y[BT * V];      // y = X3 @ rel
__device__ float g_hA[B * V * TE]; // connect output, layout [b][g][t*E+e]
__device__ float g_h3[B * HB];     // dyn output, layout [b][t][g][i]  (i in 2E)
__device__ float g_tgp[KSPLIT * BT * V]; // split-K partials for tg
__device__ float g_tg[BT * V];     // tg[bt][v]
__device__ float g_gt[B * V * NPRE]; // gt[b*V+g][o]  (o = T = 12)

__device__ __forceinline__ float leakyf(float x) { return x >= 0.f ? x : 0.3f * x; }

// ---------------- f32x2 packed helpers ---------------------------------------
__device__ __forceinline__ ull pack2(float lo, float hi) {
    ull r;
    asm("mov.b64 %0, {%1, %2};" : "=l"(r) : "f"(lo), "f"(hi));
    return r;
}
__device__ __forceinline__ void unpack2(ull v, float& lo, float& hi) {
    asm("mov.b64 {%0, %1}, %2;" : "=f"(lo), "=f"(hi) : "l"(v));
}
__device__ __forceinline__ void fma2(ull& d, ull a, ull b) {
    asm("fma.rn.f32x2 %0, %1, %2, %0;" : "+l"(d) : "l"(a), "l"(b));
}

// ---------------- K0a: gather rpe + transpose -------------------------------
__global__ void k_gather(const float* __restrict__ srpe, const int* __restrict__ sdist) {
    int i = blockIdx.x * 256 + threadIdx.x;
    if (i < VV) {
        float v = srpe[sdist[i]];
        g_rpe[i] = v;
        g_rpeT[(i % V) * V + (i / V)] = v;
    }
}

// ---------------- K0b: rel = relu(rpe @ rpe^T), rowsum ----------------------
__global__ void k_rel() {
    __shared__ float s[V];
    __shared__ float red[256];
    int v = blockIdx.x;
    for (int k = threadIdx.x; k < V; k += 256) s[k] = g_rpe[v * V + k];
    __syncthreads();
    float lr = 0.f;
    for (int g = threadIdx.x; g < V; g += 256) {
        float sum = 0.f;
        for (int k = 0; k < V; k++) sum += s[k] * g_rpeT[k * V + g];
        float r = sum > 0.f ? sum : 0.f;
        g_rel[v * V + g] = r;
        lr += r;
    }
    red[threadIdx.x] = lr;
    __syncthreads();
    for (int st = 128; st > 0; st >>= 1) {
        if (threadIdx.x < st) red[threadIdx.x] += red[threadIdx.x + st];
        __syncthreads();
    }
    if (threadIdx.x == 0) g_rsum[v] = red[0];
}

// ---------------- K1x: extract dense x3 [bt][v] -----------------------------
__global__ void k_x3(const float* __restrict__ inp) {
    int idx = blockIdx.x * 256 + threadIdx.x;
    if (idx >= BT * V) return;
    int bt = idx / V, v = idx % V;
    int b = bt / T, t = bt % T;
    g_x3d[idx] = inp[b * IN_B + (1 + t) * IN_ROW + 2 + v];
}

// ---------------- small SGEMM tile core (64x64, BK=16) for k_sgemm_y --------
__device__ __forceinline__ void gemm_tile(
    const float* __restrict__ A, int lda, int M,
    const float* __restrict__ Bm, int ldb, int N,
    int m0, int n0, int kbeg, int kend, float acc[4][4])
{
    __shared__ float sA[16 * 64];
    __shared__ float sB[16 * 64];
    int tid = threadIdx.x;
    int tm = (tid >> 4) << 2;
    int tn = (tid & 15) << 2;
    for (int k0 = kbeg; k0 < kend; k0 += 16) {
        #pragma unroll
        for (int i = 0; i < 4; i++) {
            int idx = tid + i * 256;
            int m = idx >> 4;
            int kk = idx & 15;
            int gm = m0 + m, gk = k0 + kk;
            float v = (gm < M && gk < kend) ? A[(size_t)gm * lda + gk] : 0.f;
            sA[kk * 64 + m] = v;
        }
        #pragma unroll
        for (int i = 0; i < 4; i++) {
            int idx = tid + i * 256;
            int kk = idx >> 6;
            int n = idx & 63;
            int gk = k0 + kk, gn = n0 + n;
            float v = (gk < kend && gn < N) ? Bm[(size_t)gk * ldb + gn] : 0.f;
            sB[kk * 64 + n] = v;
        }
        __syncthreads();
        #pragma unroll
        for (int kk = 0; kk < 16; kk++) {
            float4 a4 = *(const float4*)(sA + kk * 64 + tm);
            float4 b4 = *(const float4*)(sB + kk * 64 + tn);
            float av[4] = {a4.x, a4.y, a4.z, a4.w};
            float bv[4] = {b4.x, b4.y, b4.z, b4.w};
            #pragma unroll
            for (int x = 0; x < 4; x++)
                #pragma unroll
                for (int y = 0; y < 4; y++)
                    acc[x][y] += av[x] * bv[y];
        }
        __syncthreads();
    }
}

// ---------------- big SGEMM core: 128x128 tile, BK=16, 8x8/thread, f32x2 ----
// acc[x][p] packs output columns (2p, 2p+1) of the thread's 8-col set.
// Thread col y -> global n = n0 + (y<4 ? tn*4+y : 64+tn*4+y-4); same for rows.
__device__ __forceinline__ void gemm128(
    float* sA, float* sB,
    const float* __restrict__ A, int lda, int M,
    const float* __restrict__ Bm, int ldb, int N,
    int m0, int n0, int kbeg, int kend, ull acc[8][4])
{
    int tid = threadIdx.x;
    int tm = tid >> 4, tn = tid & 15;
    int arow = tid >> 2;            // 0..63
    int acol = (tid & 3) << 2;      // 0,4,8,12
    int brow = tid >> 5;            // 0..7
    int bcol = (tid & 31) << 2;     // 0..124

    for (int k0 = kbeg; k0 < kend; k0 += BKK) {
        // load A tile 128x16 (row-major) -> sA[k][m]
        #pragma unroll
        for (int i = 0; i < 2; i++) {
            int m = arow + i * 64;
            int gm = m0 + m;
            int gk = k0 + acol;
            float4 v = make_float4(0.f, 0.f, 0.f, 0.f);
            if (gm < M && gk < kend)
                v = *(const float4*)(A + (size_t)gm * lda + gk);
            sA[(acol + 0) * BM + m] = v.x;
            sA[(acol + 1) * BM + m] = v.y;
            sA[(acol + 2) * BM + m] = v.z;
            sA[(acol + 3) * BM + m] = v.w;
        }
        // load B tile 16x128 -> sB[k][n]  (scalar: ldb may be odd)
        #pragma unroll
        for (int i = 0; i < 2; i++) {
            int kk = brow + i * 8;
            int gk = k0 + kk;
            bool kok = gk < kend;
            const float* src = Bm + (size_t)gk * ldb + n0 + bcol;
            float* dst = sB + kk * BN + bcol;
            #pragma unroll
            for (int j = 0; j < 4; j++) {
                int gn = n0 + bcol + j;
                dst[j] = (kok && gn < N) ? src[j] : 0.f;
            }
        }
        __syncthreads();
        #pragma unroll
        for (int kk = 0; kk < BKK; kk++) {
            float4 a0 = *(const float4*)(sA + kk * BM + tm * 4);
            float4 a1 = *(const float4*)(sA + kk * BM + 64 + tm * 4);
            float4 b0 = *(const float4*)(sB + kk * BN + tn * 4);
            float4 b1 = *(const float4*)(sB + kk * BN + 64 + tn * 4);
            ull bp[4];
            bp[0] = pack2(b0.x, b0.y);
            bp[1] = pack2(b0.z, b0.w);
            bp[2] = pack2(b1.x, b1.y);
            bp[3] = pack2(b1.z, b1.w);
            float av[8] = {a0.x, a0.y, a0.z, a0.w, a1.x, a1.y, a1.z, a1.w};
            #pragma unroll
            for (int x = 0; x < 8; x++) {
                ull ax = pack2(av[x], av[x]);
                #pragma unroll
                for (int p = 0; p < 4; p++) fma2(acc[x][p], ax, bp[p]);
            }
        }
        __syncthreads();
    }
}

__device__ __forceinline__ int map8(int base, int t4, int x) {
    return base + ((x < 4) ? (t4 + x) : (64 + t4 + x - 4));
}

// ---------------- K1: y = X3 (1536x307) @ rel (307x307) ---------------------
__global__ void k_sgemm_y() {
    float acc[4][4] = {};
    int m0 = blockIdx.y * 64, n0 = blockIdx.x * 64;
    gemm_tile(g_x3d, V, BT, g_rel, V, V, m0, n0, 0, V, acc);
    int tid = threadIdx.x;
    int tm = (tid >> 4) << 2, tn = (tid & 15) << 2;
    #pragma unroll
    for (int x = 0; x < 4; x++) {
        int m = m0 + tm + x;
        if (m >= BT) continue;
        #pragma unroll
        for (int y = 0; y < 4; y++) {
            int n = n0 + tn + y;
            if (n < V) g_y[m * V + n] = acc[x][y];
        }
    }
}

// ---------------- K2: connect layer (per (v,t): 128x96 @ 96x32) -------------
__global__ void __launch_bounds__(128) k_connect(
    const float* __restrict__ inp,
    const float* __restrict__ conv_w, const float* __restrict__ conv_b,
    const float* __restrict__ sape, const float* __restrict__ dow,
    const float* __restrict__ tod,
    const float* __restrict__ cw, const float* __restrict__ cb)
{
    int v = blockIdx.x, t = blockIdx.y;
    __shared__ float s_cw[96 * 32];
    __shared__ float s_cb[32], s_w[32], s_b[32];
    const float* cwp = cw + (size_t)(t * V + v) * 96 * 32;
    for (int i = threadIdx.x; i < 3072; i += 128) s_cw[i] = cwp[i];
    if (threadIdx.x < 32) {
        s_cb[threadIdx.x] = cb[(t * V + v) * 32 + threadIdx.x];
        s_w[threadIdx.x] = conv_w[threadIdx.x];
        s_b[threadIdx.x] = conv_b[threadIdx.x];
    }
    __syncthreads();
    int b = threadIdx.x;
    float yv = g_y[(b * T + t) * V + v];
    float rv = g_rsum[v];
    int nr = (int)inp[b * IN_B + 2 + v];
    int sw = (int)inp[b * IN_B + (1 + t) * IN_ROW + 0];
    int sd = (int)inp[b * IN_B + (1 + t) * IN_ROW + 1];
    const float* sp = sape + (nr * T + t) * E;
    const float* dwp = dow + (sw * V + v) * E;
    const float* tdp = tod + (sd * V + v) * E;

    float acc[32];
    #pragma unroll
    for (int e = 0; e < 32; e++) acc[e] = s_cb[e];

    #pragma unroll
    for (int f = 0; f < 32; f++) {
        float xf = yv * s_w[f] + rv * s_b[f];
        const float4* c4 = (const float4*)(s_cw + f * 32);
        #pragma unroll
        for (int e4 = 0; e4 < 8; e4++) {
            float4 w4 = c4[e4];
            acc[e4 * 4 + 0] += xf * w4.x; acc[e4 * 4 + 1] += xf * w4.y;
            acc[e4 * 4 + 2] += xf * w4.z; acc[e4 * 4 + 3] += xf * w4.w;
        }
    }
    #pragma unroll
    for (int f = 0; f < 32; f++) {
        float xf = sp[f];
        const float4* c4 = (const float4*)(s_cw + (32 + f) * 32);
        #pragma unroll
        for (int e4 = 0; e4 < 8; e4++) {
            float4 w4 = c4[e4];
            acc[e4 * 4 + 0] += xf * w4.x; acc[e4 * 4 + 1] += xf * w4.y;
            acc[e4 * 4 + 2] += xf * w4.z; acc[e4 * 4 + 3] += xf * w4.w;
        }
    }
    #pragma unroll
    for (int f = 0; f < 32; f++) {
        float xf = dwp[f] + tdp[f];
        const float4* c4 = (const float4*)(s_cw + (64 + f) * 32);
        #pragma unroll
        for (int e4 = 0; e4 < 8; e4++) {
            float4 w4 = c4[e4];
            acc[e4 * 4 + 0] += xf * w4.x; acc[e4 * 4 + 1] += xf * w4.y;
            acc[e4 * 4 + 2] += xf * w4.z; acc[e4 * 4 + 3] += xf * w4.w;
        }
    }
    float* o = g_hA + (size_t)(b * V + v) * TE + t * E;
    #pragma unroll
    for (int e = 0; e < 32; e++) o[e] = leakyf(acc[e]);
}

// ---------------- K3: dynamic layer, per b: A(307x384)@(W1+W2)(384x768) -----
__global__ void __launch_bounds__(256, 2) k_dyn(
    const float* __restrict__ inp,
    const float* __restrict__ w1all, const float* __restrict__ w2all,
    const float* __restrict__ o1all, const float* __restrict__ o2all)
{
    __shared__ float sA[BKK * BM];
    __shared__ float sB[BKK * BN];
    int b = blockIdx.z;
    int wk = (int)inp[b * IN_B + 0];
    int dt = (int)inp[b * IN_B + 1];
    int m0 = blockIdx.y * BM, n0 = blockIdx.x * BN;
    ull acc[8][4];
    #pragma unroll
    for (int x = 0; x < 8; x++)
        #pragma unroll
        for (int p = 0; p < 4; p++) acc[x][p] = 0ull;

    const float* A = g_hA + (size_t)b * V * TE;
    gemm128(sA, sB, A, TE, V, w1all + (size_t)wk * TE * N2, N2, N2, m0, n0, 0, TE, acc);
    gemm128(sA, sB, A, TE, V, w2all + (size_t)dt * TE * N2, N2, N2, m0, n0, 0, TE, acc);

    int tid = threadIdx.x;
    int tm4 = (tid >> 4) << 2, tn4 = (tid & 15) << 2;
    const float* b1 = o1all + (size_t)wk * HB;
    const float* b2 = o2all + (size_t)dt * HB;
    float* h3 = g_h3 + (size_t)b * HB;
    #pragma unroll
    for (int x = 0; x < 8; x++) {
        int g = map8(m0, tm4, x);
        if (g >= V) continue;
        #pragma unroll
        for (int p = 0; p < 4; p++) {
            float v2[2];
            unpack2(acc[x][p], v2[0], v2[1]);
            #pragma unroll
            for (int q = 0; q < 2; q++) {
                int y = 2 * p + q;
                int n = map8(n0, tn4, y);   // n < 768 always
                float val = 0.5f * (v2[q] + b1[g * N2 + n] + b2[g * N2 + n]);
                val = leakyf(val);
                int i = n / 12, j = n % 12;
                h3[j * VE2 + g * 64 + i] = val;
            }
        }
    }
}

// ---------------- K4: tg = H3(1536x19648) @ tge2tg(19648x307), split-K ------
__global__ void __launch_bounds__(256, 2) k_tg(const float* __restrict__ t2t) {
    __shared__ float sA[BKK * BM];
    __shared__ float sB[BKK * BN];
    int ks = blockIdx.z;
    int m0 = blockIdx.y * BM, n0 = blockIdx.x * BN;
    ull acc[8][4];
    #pragma unroll
    for (int x = 0; x < 8; x++)
        #pragma unroll
        for (int p = 0; p < 4; p++) acc[x][p] = 0ull;

    gemm128(sA, sB, g_h3, VE2, BT, t2t, V, V, m0, n0, ks * KCH, (ks + 1) * KCH, acc);

    int tid = threadIdx.x;
    int tm4 = (tid >> 4) << 2, tn4 = (tid & 15) << 2;
    float* p = g_tgp + (size_t)ks * BT * V;
    #pragma unroll
    for (int x = 0; x < 8; x++) {
        int m = map8(m0, tm4, x);      // m < 1536 always (12 tiles exact)
        #pragma unroll
        for (int pp = 0; pp < 4; pp++) {
            float v2[2];
            unpack2(acc[x][pp], v2[0], v2[1]);
            #pragma unroll
            for (int q = 0; q < 2; q++) {
                int y = 2 * pp + q;
                int n = map8(n0, tn4, y);
                if (n < V) p[m * V + n] = v2[q];
            }
        }
    }
}

__global__ void k_tgr() {
    int i = blockIdx.x * 256 + threadIdx.x;
    if (i < BT * V) {
        float s = 0.f;
        #pragma unroll
        for (int k = 0; k < KSPLIT; k++) s += g_tgp[(size_t)k * BT * V + i];
        g_tg[i] = s;
    }
}

// ---------------- K5: gt = rows(H3 as (B*V)x768) @ gte2gt(768x12) -----------
__global__ void k_gt(const float* __restrict__ g2g) {
    __shared__ float s[N2 * NPRE]; // 9216 floats = 36KB
    for (int i = threadIdx.x; i < N2 * NPRE; i += 256) s[i] = g2g[i];
    __syncthreads();
    int wid = threadIdx.x >> 5, lane = threadIdx.x & 31;
    int r = blockIdx.x * 8 + wid;
    const float* row = g_h3 + (size_t)r * N2;
    float acc[NPRE] = {};
    for (int m = lane; m < N2; m += 32) {
        float a = row[m];
        const float* sm = s + m * NPRE;
        #pragma unroll
        for (int o = 0; o < NPRE; o++) acc[o] += a * sm[o];
    }
    #pragma unroll
    for (int o = 0; o < NPRE; o++) {
        #pragma unroll
        for (int st = 16; st > 0; st >>= 1)
            acc[o] += __shfl_xor_sync(0xffffffffu, acc[o], st);
    }
    if (lane == 0) {
        #pragma unroll
        for (int o = 0; o < NPRE; o++) g_gt[r * NPRE + o] = acc[o];
    }
}

// ---------------- K6: gates + weight1/2 + fully, write transposed out -------
__global__ void k_out(const float* __restrict__ w1, const float* __restrict__ w2,
                      const float* __restrict__ fw, const float* __restrict__ fb,
                      float* __restrict__ out)
{
    int idx = blockIdx.x * 256 + threadIdx.x;
    if (idx >= B * V) return;
    int b = idx / V, g = idx % V;
    float gt1[T], gt2[T];
    #pragma unroll
    for (int t = 0; t < T; t++) {
        float x3v = g_x3d[(b * T + t) * V + g];
        float tgv = g_tg[(b * T + t) * V + g];
        float gtv = g_gt[idx * NPRE + t];
        gt1[t] = (tgv + x3v) * (1.f / (1.f + expf(-tgv)));
        gt2[t] = (gtv + x3v) * (1.f / (1.f + expf(-gtv)));
    }
    float x1[NPRE], x2[NPRE];
    #pragma unroll
    for (int o = 0; o < NPRE; o++) { x1[o] = 0.f; x2[o] = 0.f; }
    #pragma unroll
    for (int i = 0; i < T; i++) {
        float a = gt1[i], c = gt2[i];
        #pragma unroll
        for (int o = 0; o < NPRE; o++) {
            x1[o] += w1[g * 144 + i * 12 + o] * a;
            x2[o] += w2[g * 144 + i * 12 + o] * c;
        }
    }
    #pragma unroll
    for (int o = 0; o < NPRE; o++) {
        float sacc = fb[o];
        #pragma unroll
        for (int i = 0; i < NPRE; i++) {
            sacc += x1[i] * fw[i * 12 + o] + x2[i] * fw[(12 + i) * 12 + o];
        }
        out[(size_t)b * NPRE * V + o * V + g] = sacc;
    }
}

// ---------------- launch -----------------------------------------------------
extern "C" void kernel_launch(void* const* d_in, const int* in_sizes, int n_in,
                              void* d_out, int out_size) {
    const float* inputs = (const float*)d_in[0];
    const int*   sdist  = (const int*)d_in[1];
    const float* conv_w = (const float*)d_in[2];
    const float* conv_b = (const float*)d_in[3];
    const float* srpe   = (const float*)d_in[4];
    const float* sape   = (const float*)d_in[5];
    const float* dow    = (const float*)d_in[6];
    const float* tod    = (const float*)d_in[7];
    const float* cw     = (const float*)d_in[8];
    const float* cb     = (const float*)d_in[9];
    const float* dw1    = (const float*)d_in[10];
    const float* do1    = (const float*)d_in[11];
    const float* dw2    = (const float*)d_in[12];
    const float* do2    = (const float*)d_in[13];
    const float* t2t    = (const float*)d_in[14];
    const float* g2g    = (const float*)d_in[15];
    const float* w1     = (const float*)d_in[16];
    const float* w2     = (const float*)d_in[17];
    const float* fw     = (const float*)d_in[18];
    const float* fb     = (const float*)d_in[19];
    float* out = (float*)d_out;

    k_gather<<<(VV + 255) / 256, 256>>>(srpe, sdist);
    k_rel<<<V, 256>>>();
    k_x3<<<(BT * V + 255) / 256, 256>>>(inputs);
    k_sgemm_y<<<dim3(5, 24), 256>>>();
    k_connect<<<dim3(V, T), 128>>>(inputs, conv_w, conv_b, sape, dow, tod, cw, cb);
    k_dyn<<<dim3(6, 3, B), 256>>>(inputs, dw1, dw2, do1, do2);
    k_tg<<<dim3(3, 12, KSPLIT), 256>>>(t2t);
    k_tgr<<<(BT * V + 255) / 256, 256>>>();
    k_gt<<<(B * V) / 8, 256>>>(g2g);
    k_out<<<(B * V + 255) / 256, 256>>>(w1, w2, fw, fb, out);
}

// round 11
// speedup vs baseline: 1.7602x; 1.2317x over previous
#include <cuda_runtime.h>
#include <cuda_bf16.h>
#include <math.h>
#include <stdint.h>

#define V 307
#define T 12
#define E 32
#define B 128
#define NPRE 12
#define TE 384      // T*E
#define N2 768      // 2E*T
#define VE2 19648   // V*2E
#define VV 94249    // V*V
#define BT 1536     // B*T
#define IN_ROW 309
#define IN_B 4017   // 13*309
#define HB 235776   // V*N2 = 12*VE2
#define KSPLIT 4

#define MSTR 72     // smem row stride (bf16 elems) = 144B -> conflict-free ldmatrix

// ---------------- scratch ----------------------------------------------------
__device__ float g_rpe[VV];
__device__ float g_rpeT[VV];
__device__ float g_rel[VV];
__device__ float g_rsum[V];
__device__ float g_x3d[BT * V];
__device__ float g_y[BT * V];
__device__ float g_hA[B * V * TE];           // [b][g][t*E+e]
__device__ float g_h3[(size_t)B * HB];       // [b][j][g][i]  (reference-contiguous)
__device__ float g_tgp[KSPLIT * BT * V];
__device__ float g_tg[BT * V];
__device__ float g_gt[B * V * NPRE];
// bf16 hi/lo operand images for mma GEMMs
__device__ unsigned short g_Ahd[(size_t)B * 384 * TE];   // dyn A  [b][row384][k384]
__device__ unsigned short g_Ald[(size_t)B * 384 * TE];
__device__ unsigned short g_Whd[(size_t)B * N2 * TE];    // dyn B' [b][n768][k384]
__device__ unsigned short g_Wld[(size_t)B * N2 * TE];
__device__ unsigned short g_h3h[(size_t)BT * VE2];       // tg A   [bt][k19648]
__device__ unsigned short g_h3l[(size_t)BT * VE2];
__device__ unsigned short g_Th[(size_t)384 * VE2];       // tg B'  [v384][k19648]
__device__ unsigned short g_Tl[(size_t)384 * VE2];

__device__ __forceinline__ float leakyf(float x) { return x >= 0.f ? x : 0.3f * x; }

__device__ __forceinline__ uint32_t smem_u32(const void* p) {
    uint32_t a;
    asm("{ .reg .u64 t; cvta.to.shared.u64 t, %1; cvt.u32.u64 %0, t; }" : "=r"(a) : "l"(p));
    return a;
}
__device__ __forceinline__ void ldsm_x4(uint32_t& r0, uint32_t& r1, uint32_t& r2, uint32_t& r3, uint32_t addr) {
    asm volatile("ldmatrix.sync.aligned.m8n8.x4.shared.b16 {%0,%1,%2,%3}, [%4];"
        : "=r"(r0), "=r"(r1), "=r"(r2), "=r"(r3) : "r"(addr));
}
__device__ __forceinline__ void mma16816(float* c, const uint32_t* a, uint32_t b0, uint32_t b1) {
    asm volatile("mma.sync.aligned.m16n8k16.row.col.f32.bf16.bf16.f32 "
        "{%0,%1,%2,%3}, {%4,%5,%6,%7}, {%8,%9}, {%0,%1,%2,%3};"
        : "+f"(c[0]), "+f"(c[1]), "+f"(c[2]), "+f"(c[3])
        : "r"(a[0]), "r"(a[1]), "r"(a[2]), "r"(a[3]), "r"(b0), "r"(b1));
}
__device__ __forceinline__ void bf16split(float x, unsigned short& hb, unsigned short& lb) {
    __nv_bfloat16 h = __float2bfloat16(x);
    float r = x - __bfloat162float(h);
    __nv_bfloat16 l = __float2bfloat16(r);
    hb = *(unsigned short*)&h;
    lb = *(unsigned short*)&l;
}

// ---------------- mma GEMM core: 128x128 tile, BK=64, 3-pass hi/lo ----------
// Computes C[m0+..][n0+..] += sum over 3 passes x K of A*B'
// A images row-major [M][lda] (k contiguous); B' images [N][ldb] (k contiguous).
// Pass p: A-src = (p==1 ? Al : Ah), B-src = (p==2 ? Bl : Bh).
__device__ __forceinline__ void mma_gemm(
    const unsigned short* __restrict__ Ah, const unsigned short* __restrict__ Al, size_t lda,
    const unsigned short* __restrict__ Bh, const unsigned short* __restrict__ Bl, size_t ldb,
    int m0, int n0, int kbeg, int nch,
    unsigned short* sA, unsigned short* sB, float acc[4][4][4])
{
    int tid = threadIdx.x;
    int lane = tid & 31, wid = tid >> 5;
    int wm = (wid & 1) * 64, wn = (wid >> 1) * 32;
    uint32_t sAu = smem_u32(sA), sBu = smem_u32(sB);
    int seg = tid & 7, rb = tid >> 3;
    int NIT = 3 * nch;
    uint4 pa[4], pb[4];

    auto gload = [&](int it) {
        int p = it / nch, c = it - p * nch;
        size_t k0 = (size_t)kbeg + c * 64 + seg * 8;
        const unsigned short* As = (p == 1) ? Al : Ah;
        const unsigned short* Bs = (p == 2) ? Bl : Bh;
        #pragma unroll
        for (int i = 0; i < 4; i++) {
            pa[i] = *(const uint4*)(As + (size_t)(m0 + rb + 32 * i) * lda + k0);
            pb[i] = *(const uint4*)(Bs + (size_t)(n0 + rb + 32 * i) * ldb + k0);
        }
    };

    gload(0);
    for (int it = 0; it < NIT; it++) {
        #pragma unroll
        for (int i = 0; i < 4; i++) {
            *(uint4*)(sA + (rb + 32 * i) * MSTR + seg * 8) = pa[i];
            *(uint4*)(sB + (rb + 32 * i) * MSTR + seg * 8) = pb[i];
        }
        __syncthreads();
        if (it + 1 < NIT) gload(it + 1);
        #pragma unroll
        for (int k16 = 0; k16 < 4; k16++) {
            uint32_t a[4][4], bfm[2][4];
            uint32_t acol = (uint32_t)(k16 * 16 + (lane >> 4) * 8) * 2;
            #pragma unroll
            for (int mi = 0; mi < 4; mi++)
                ldsm_x4(a[mi][0], a[mi][1], a[mi][2], a[mi][3],
                        sAu + (uint32_t)(wm + mi * 16 + (lane & 15)) * (MSTR * 2) + acol);
            uint32_t brow = (lane & 7) + (lane >> 4) * 8;
            uint32_t bcol = (uint32_t)(k16 * 16 + ((lane >> 3) & 1) * 8) * 2;
            #pragma unroll
            for (int nj = 0; nj < 2; nj++)
                ldsm_x4(bfm[nj][0], bfm[nj][1], bfm[nj][2], bfm[nj][3],
                        sBu + (uint32_t)(wn + nj * 16 + brow) * (MSTR * 2) + bcol);
            #pragma unroll
            for (int mi = 0; mi < 4; mi++)
                #pragma unroll
                for (int ni = 0; ni < 4; ni++)
                    mma16816(acc[mi][ni], a[mi], bfm[ni >> 1][(ni & 1) * 2], bfm[ni >> 1][(ni & 1) * 2 + 1]);
        }
        __syncthreads();
    }
}

// ---------------- K0a: gather rpe + transpose -------------------------------
__global__ void k_gather(const float* __restrict__ srpe, const int* __restrict__ sdist) {
    int i = blockIdx.x * 256 + threadIdx.x;
    if (i < VV) {
        float v = srpe[sdist[i]];
        g_rpe[i] = v;
        g_rpeT[(i % V) * V + (i / V)] = v;
    }
}

// ---------------- K0b: rel = relu(rpe @ rpe^T), rowsum ----------------------
__global__ void k_rel() {
    __shared__ float s[V];
    __shared__ float red[256];
    int v = blockIdx.x;
    for (int k = threadIdx.x; k < V; k += 256) s[k] = g_rpe[v * V + k];
    __syncthreads();
    float lr = 0.f;
    for (int g = threadIdx.x; g < V; g += 256) {
        float sum = 0.f;
        for (int k = 0; k < V; k++) sum += s[k] * g_rpeT[k * V + g];
        float r = sum > 0.f ? sum : 0.f;
        g_rel[v * V + g] = r;
        lr += r;
    }
    red[threadIdx.x] = lr;
    __syncthreads();
    for (int st = 128; st > 0; st >>= 1) {
        if (threadIdx.x < st) red[threadIdx.x] += red[threadIdx.x + st];
        __syncthreads();
    }
    if (threadIdx.x == 0) g_rsum[v] = red[0];
}

// ---------------- K1x: extract dense x3 [bt][v] -----------------------------
__global__ void k_x3(const float* __restrict__ inp) {
    int idx = blockIdx.x * 256 + threadIdx.x;
    if (idx >= BT * V) return;
    int bt = idx / V, v = idx % V;
    int b = bt / T, t = bt % T;
    g_x3d[idx] = inp[b * IN_B + (1 + t) * IN_ROW + 2 + v];
}

// ---------------- small SGEMM tile core (64x64, BK=16) ----------------------
__device__ __forceinline__ void gemm_tile(
    const float* __restrict__ A, int lda, int M,
    const float* __restrict__ Bm, int ldb, int N,
    int m0, int n0, int kbeg, int kend, float acc[4][4])
{
    __shared__ float sA[16 * 64];
    __shared__ float sB[16 * 64];
    int tid = threadIdx.x;
    int tm = (tid >> 4) << 2;
    int tn = (tid & 15) << 2;
    for (int k0 = kbeg; k0 < kend; k0 += 16) {
        #pragma unroll
        for (int i = 0; i < 4; i++) {
            int idx = tid + i * 256;
            int m = idx >> 4;
            int kk = idx & 15;
            int gm = m0 + m, gk = k0 + kk;
            float v = (gm < M && gk < kend) ? A[(size_t)gm * lda + gk] : 0.f;
            sA[kk * 64 + m] = v;
        }
        #pragma unroll
        for (int i = 0; i < 4; i++) {
            int idx = tid + i * 256;
            int kk = idx >> 6;
            int n = idx & 63;
            int gk = k0 + kk, gn = n0 + n;
            float v = (gk < kend && gn < N) ? Bm[(size_t)gk * ldb + gn] : 0.f;
            sB[kk * 64 + n] = v;
        }
        __syncthreads();
        #pragma unroll
        for (int kk = 0; kk < 16; kk++) {
            float4 a4 = *(const float4*)(sA + kk * 64 + tm);
            float4 b4 = *(const float4*)(sB + kk * 64 + tn);
            float av[4] = {a4.x, a4.y, a4.z, a4.w};
            float bv[4] = {b4.x, b4.y, b4.z, b4.w};
            #pragma unroll
            for (int x = 0; x < 4; x++)
                #pragma unroll
                for (int y = 0; y < 4; y++)
                    acc[x][y] += av[x] * bv[y];
        }
        __syncthreads();
    }
}

// ---------------- K1: y = X3 (1536x307) @ rel (307x307) ---------------------
__global__ void k_sgemm_y() {
    float acc[4][4] = {};
    int m0 = blockIdx.y * 64, n0 = blockIdx.x * 64;
    gemm_tile(g_x3d, V, BT, g_rel, V, V, m0, n0, 0, V, acc);
    int tid = threadIdx.x;
    int tm = (tid >> 4) << 2, tn = (tid & 15) << 2;
    #pragma unroll
    for (int x = 0; x < 4; x++) {
        int m = m0 + tm + x;
        if (m >= BT) continue;
        #pragma unroll
        for (int y = 0; y < 4; y++) {
            int n = n0 + tn + y;
            if (n < V) g_y[m * V + n] = acc[x][y];
        }
    }
}

// ---------------- K2: connect layer ------------------------------------------
__global__ void __launch_bounds__(128) k_connect(
    const float* __restrict__ inp,
    const float* __restrict__ conv_w, const float* __restrict__ conv_b,
    const float* __restrict__ sape, const float* __restrict__ dow,
    const float* __restrict__ tod,
    const float* __restrict__ cw, const float* __restrict__ cb)
{
    int v = blockIdx.x, t = blockIdx.y;
    __shared__ float s_cw[96 * 32];
    __shared__ float s_cb[32], s_w[32], s_b[32];
    const float* cwp = cw + (size_t)(t * V + v) * 96 * 32;
    for (int i = threadIdx.x; i < 3072; i += 128) s_cw[i] = cwp[i];
    if (threadIdx.x < 32) {
        s_cb[threadIdx.x] = cb[(t * V + v) * 32 + threadIdx.x];
        s_w[threadIdx.x] = conv_w[threadIdx.x];
        s_b[threadIdx.x] = conv_b[threadIdx.x];
    }
    __syncthreads();
    int b = threadIdx.x;
    float yv = g_y[(b * T + t) * V + v];
    float rv = g_rsum[v];
    int nr = (int)inp[b * IN_B + 2 + v];
    int sw = (int)inp[b * IN_B + (1 + t) * IN_ROW + 0];
    int sd = (int)inp[b * IN_B + (1 + t) * IN_ROW + 1];
    const float* sp = sape + (nr * T + t) * E;
    const float* dwp = dow + (sw * V + v) * E;
    const float* tdp = tod + (sd * V + v) * E;

    float acc[32];
    #pragma unroll
    for (int e = 0; e < 32; e++) acc[e] = s_cb[e];

    #pragma unroll
    for (int f = 0; f < 32; f++) {
        float xf = yv * s_w[f] + rv * s_b[f];
        const float4* c4 = (const float4*)(s_cw + f * 32);
        #pragma unroll
        for (int e4 = 0; e4 < 8; e4++) {
            float4 w4 = c4[e4];
            acc[e4 * 4 + 0] += xf * w4.x; acc[e4 * 4 + 1] += xf * w4.y;
            acc[e4 * 4 + 2] += xf * w4.z; acc[e4 * 4 + 3] += xf * w4.w;
        }
    }
    #pragma unroll
    for (int f = 0; f < 32; f++) {
        float xf = sp[f];
        const float4* c4 = (const float4*)(s_cw + (32 + f) * 32);
        #pragma unroll
        for (int e4 = 0; e4 < 8; e4++) {
            float4 w4 = c4[e4];
            acc[e4 * 4 + 0] += xf * w4.x; acc[e4 * 4 + 1] += xf * w4.y;
            acc[e4 * 4 + 2] += xf * w4.z; acc[e4 * 4 + 3] += xf * w4.w;
        }
    }
    #pragma unroll
    for (int f = 0; f < 32; f++) {
        float xf = dwp[f] + tdp[f];
        const float4* c4 = (const float4*)(s_cw + (64 + f) * 32);
        #pragma unroll
        for (int e4 = 0; e4 < 8; e4++) {
            float4 w4 = c4[e4];
            acc[e4 * 4 + 0] += xf * w4.x; acc[e4 * 4 + 1] += xf * w4.y;
            acc[e4 * 4 + 2] += xf * w4.z; acc[e4 * 4 + 3] += xf * w4.w;
        }
    }
    float* o = g_hA + (size_t)(b * V + v) * TE + t * E;
    #pragma unroll
    for (int e = 0; e < 32; e++) o[e] = leakyf(acc[e]);
}

// ---------------- pack: hA -> dyn A images (pad rows to 384) -----------------
__global__ void __launch_bounds__(256) k_packA() {
    int idx = blockIdx.x * 256 + threadIdx.x;   // B*384*48 tasks
    if (idx >= B * 384 * 48) return;
    int seg = idx % 48;
    int rem = idx / 48;
    int row = rem % 384;
    int b = rem / 384;
    union { unsigned short u[8]; uint4 v; } ph, pl;
    if (row < V) {
        const float* src = g_hA + ((size_t)b * V + row) * TE + seg * 8;
        #pragma unroll
        for (int j = 0; j < 8; j++) bf16split(src[j], ph.u[j], pl.u[j]);
    } else {
        ph.v = make_uint4(0, 0, 0, 0);
        pl.v = make_uint4(0, 0, 0, 0);
    }
    size_t o = ((size_t)b * 384 + row) * TE + seg * 8;
    *(uint4*)(g_Ahd + o) = ph.v;
    *(uint4*)(g_Ald + o) = pl.v;
}

// ---------------- pack: Wsum = W1[wk]+W2[dt], transposed to [n][k] -----------
__global__ void __launch_bounds__(256) k_packW(
    const float* __restrict__ inp,
    const float* __restrict__ w1all, const float* __restrict__ w2all)
{
    __shared__ float s[64 * 129];
    int nt = blockIdx.x, kc = blockIdx.y, b = blockIdx.z;
    int n0 = nt * 128, k0 = kc * 64;
    int wk = (int)inp[b * IN_B + 0];
    int dt = (int)inp[b * IN_B + 1];
    const float* w1p = w1all + (size_t)wk * TE * N2;
    const float* w2p = w2all + (size_t)dt * TE * N2;
    for (int idx = threadIdx.x; idx < 8192; idx += 256) {
        int k = idx >> 7, n = idx & 127;
        size_t g = (size_t)(k0 + k) * N2 + n0 + n;
        s[k * 129 + n] = w1p[g] + w2p[g];
    }
    __syncthreads();
    for (int t2 = threadIdx.x; t2 < 1024; t2 += 256) {
        int n = t2 >> 3, seg = t2 & 7;
        union { unsigned short u[8]; uint4 v; } ph, pl;
        #pragma unroll
        for (int j = 0; j < 8; j++) bf16split(s[(seg * 8 + j) * 129 + n], ph.u[j], pl.u[j]);
        size_t o = ((size_t)b * N2 + n0 + n) * TE + k0 + seg * 8;
        *(uint4*)(g_Whd + o) = ph.v;
        *(uint4*)(g_Wld + o) = pl.v;
    }
}

// ---------------- pack: tge2tg transpose -> [v 384][k 19648] hi/lo -----------
__global__ void __launch_bounds__(256) k_packT(const float* __restrict__ t2t) {
    __shared__ float s[64][65];
    int kc = blockIdx.x, nc = blockIdx.y;
    int k0 = kc * 64, n0 = nc * 64;
    for (int idx = threadIdx.x; idx < 4096; idx += 256) {
        int k = idx >> 6, n = idx & 63;
        s[k][n] = (n0 + n < V) ? t2t[(size_t)(k0 + k) * V + n0 + n] : 0.f;
    }
    __syncthreads();
    for (int t2 = threadIdx.x; t2 < 512; t2 += 256) {
        int n = t2 >> 3, seg = t2 & 7;
        union { unsigned short u[8]; uint4 v; } ph, pl;
        #pragma unroll
        for (int j = 0; j < 8; j++) bf16split(s[seg * 8 + j][n], ph.u[j], pl.u[j]);
        size_t o = (size_t)(n0 + n) * VE2 + k0 + seg * 8;
        *(uint4*)(g_Th + o) = ph.v;
        *(uint4*)(g_Tl + o) = pl.v;
    }
}

// ---------------- K3: dynamic layer via mma.sync ------------------------------
// grid (6 nt, 3 mt, B); C = hA @ (W1+W2) over K=384, 3-pass hi/lo
__global__ void __launch_bounds__(256, 1) k_dyn_mma(
    const float* __restrict__ inp,
    const float* __restrict__ o1all, const float* __restrict__ o2all)
{
    __shared__ unsigned short sA[128 * MSTR];
    __shared__ unsigned short sB[128 * MSTR];
    int nt = blockIdx.x, mt = blockIdx.y, b = blockIdx.z;
    int m0 = mt * 128, n0 = nt * 128;
    float acc[4][4][4];
    #pragma unroll
    for (int i = 0; i < 4; i++)
        #pragma unroll
        for (int j = 0; j < 4; j++)
            #pragma unroll
            for (int r = 0; r < 4; r++) acc[i][j][r] = 0.f;

    mma_gemm(g_Ahd + (size_t)b * 384 * TE, g_Ald + (size_t)b * 384 * TE, TE,
             g_Whd + (size_t)b * N2 * TE,  g_Wld + (size_t)b * N2 * TE,  TE,
             m0, n0, 0, TE / 64, sA, sB, acc);

    int tid = threadIdx.x, lane = tid & 31, wid = tid >> 5;
    int wm = (wid & 1) * 64, wn = (wid >> 1) * 32;
    int gr = lane >> 2, tc = (lane & 3) * 2;
    int wk = (int)inp[b * IN_B + 0];
    int dt = (int)inp[b * IN_B + 1];
    const float* b1 = o1all + (size_t)wk * HB;
    const float* b2 = o2all + (size_t)dt * HB;
    #pragma unroll
    for (int mi = 0; mi < 4; mi++) {
        #pragma unroll
        for (int h = 0; h < 2; h++) {
            int g = m0 + wm + mi * 16 + gr + h * 8;
            if (g >= V) continue;
            #pragma unroll
            for (int ni = 0; ni < 4; ni++) {
                #pragma unroll
                for (int cb = 0; cb < 2; cb++) {
                    int n = n0 + wn + ni * 8 + tc + cb;
                    float val = 0.5f * (acc[mi][ni][h * 2 + cb] + b1[g * N2 + n] + b2[g * N2 + n]);
                    val = leakyf(val);
                    int i = n / 12, j = n % 12;
                    g_h3[(size_t)b * HB + (size_t)j * VE2 + g * 64 + i] = val;
                    unsigned short hb, lb;
                    bf16split(val, hb, lb);
                    size_t to = (size_t)(b * 12 + j) * VE2 + g * 64 + i;
                    g_h3h[to] = hb;
                    g_h3l[to] = lb;
                }
            }
        }
    }
}

// ---------------- K4: tg via mma.sync, split-K -------------------------------
// grid (3 nt, 12 mt, KSPLIT)
__global__ void __launch_bounds__(256, 1) k_tg_mma() {
    __shared__ unsigned short sA[128 * MSTR];
    __shared__ unsigned short sB[128 * MSTR];
    int nt = blockIdx.x, mt = blockIdx.y, ks = blockIdx.z;
    int m0 = mt * 128, n0 = nt * 128;
    int c0 = (ks * 307) / KSPLIT, c1 = ((ks + 1) * 307) / KSPLIT;
    float acc[4][4][4];
    #pragma unroll
    for (int i = 0; i < 4; i++)
        #pragma unroll
        for (int j = 0; j < 4; j++)
            #pragma unroll
            for (int r = 0; r < 4; r++) acc[i][j][r] = 0.f;

    mma_gemm(g_h3h, g_h3l, VE2, g_Th, g_Tl, VE2, m0, n0, c0 * 64, c1 - c0, sA, sB, acc);

    int tid = threadIdx.x, lane = tid & 31, wid = tid >> 5;
    int wm = (wid & 1) * 64, wn = (wid >> 1) * 32;
    int gr = lane >> 2, tc = (lane & 3) * 2;
    float* pp = g_tgp + (size_t)ks * BT * V;
    #pragma unroll
    for (int mi = 0; mi < 4; mi++) {
        #pragma unroll
        for (int h = 0; h < 2; h++) {
            int m = m0 + wm + mi * 16 + gr + h * 8;
            #pragma unroll
            for (int ni = 0; ni < 4; ni++) {
                #pragma unroll
                for (int cb = 0; cb < 2; cb++) {
                    int n = n0 + wn + ni * 8 + tc + cb;
                    if (n < V) pp[(size_t)m * V + n] = acc[mi][ni][h * 2 + cb];
                }
            }
        }
    }
}

__global__ void k_tgr() {
    int i = blockIdx.x * 256 + threadIdx.x;
    if (i < BT * V) {
        float s = 0.f;
        #pragma unroll
        for (int k = 0; k < KSPLIT; k++) s += g_tgp[(size_t)k * BT * V + i];
        g_tg[i] = s;
    }
}

// ---------------- K5: gt = rows(H3 as (B*V)x768) @ gte2gt(768x12) -----------
__global__ void k_gt(const float* __restrict__ g2g) {
    __shared__ float s[N2 * NPRE];
    for (int i = threadIdx.x; i < N2 * NPRE; i += 256) s[i] = g2g[i];
    __syncthreads();
    int wid = threadIdx.x >> 5, lane = threadIdx.x & 31;
    int r = blockIdx.x * 8 + wid;
    const float* row = g_h3 + (size_t)r * N2;
    float acc[NPRE] = {};
    for (int m = lane; m < N2; m += 32) {
        float a = row[m];
        const float* sm = s + m * NPRE;
        #pragma unroll
        for (int o = 0; o < NPRE; o++) acc[o] += a * sm[o];
    }
    #pragma unroll
    for (int o = 0; o < NPRE; o++) {
        #pragma unroll
        for (int st = 16; st > 0; st >>= 1)
            acc[o] += __shfl_xor_sync(0xffffffffu, acc[o], st);
    }
    if (lane == 0) {
        #pragma unroll
        for (int o = 0; o < NPRE; o++) g_gt[r * NPRE + o] = acc[o];
    }
}

// ---------------- K6: gates + weight1/2 + fully -----------------------------
__global__ void k_out(const float* __restrict__ w1, const float* __restrict__ w2,
                      const float* __restrict__ fw, const float* __restrict__ fb,
                      float* __restrict__ out)
{
    int idx = blockIdx.x * 256 + threadIdx.x;
    if (idx >= B * V) return;
    int b = idx / V, g = idx % V;
    float gt1[T], gt2[T];
    #pragma unroll
    for (int t = 0; t < T; t++) {
        float x3v = g_x3d[(b * T + t) * V + g];
        float tgv = g_tg[(b * T + t) * V + g];
        float gtv = g_gt[idx * NPRE + t];
        gt1[t] = (tgv + x3v) * (1.f / (1.f + expf(-tgv)));
        gt2[t] = (gtv + x3v) * (1.f / (1.f + expf(-gtv)));
    }
    float x1[NPRE], x2[NPRE];
    #pragma unroll
    for (int o = 0; o < NPRE; o++) { x1[o] = 0.f; x2[o] = 0.f; }
    #pragma unroll
    for (int i = 0; i < T; i++) {
        float a = gt1[i], c = gt2[i];
        #pragma unroll
        for (int o = 0; o < NPRE; o++) {
            x1[o] += w1[g * 144 + i * 12 + o] * a;
            x2[o] += w2[g * 144 + i * 12 + o] * c;
        }
    }
    #pragma unroll
    for (int o = 0; o < NPRE; o++) {
        float sacc = fb[o];
        #pragma unroll
        for (int i = 0; i < NPRE; i++) {
            sacc += x1[i] * fw[i * 12 + o] + x2[i] * fw[(12 + i) * 12 + o];
        }
        out[(size_t)b * NPRE * V + o * V + g] = sacc;
    }
}

// ---------------- launch -----------------------------------------------------
extern "C" void kernel_launch(void* const* d_in, const int* in_sizes, int n_in,
                              void* d_out, int out_size) {
    const float* inputs = (const float*)d_in[0];
    const int*   sdist  = (const int*)d_in[1];
    const float* conv_w = (const float*)d_in[2];
    const float* conv_b = (const float*)d_in[3];
    const float* srpe   = (const float*)d_in[4];
    const float* sape   = (const float*)d_in[5];
    const float* dow    = (const float*)d_in[6];
    const float* tod    = (const float*)d_in[7];
    const float* cw     = (const float*)d_in[8];
    const float* cb     = (const float*)d_in[9];
    const float* dw1    = (const float*)d_in[10];
    const float* do1    = (const float*)d_in[11];
    const float* dw2    = (const float*)d_in[12];
    const float* do2    = (const float*)d_in[13];
    const float* t2t    = (const float*)d_in[14];
    const float* g2g    = (const float*)d_in[15];
    const float* w1     = (const float*)d_in[16];
    const float* w2     = (const float*)d_in[17];
    const float* fw     = (const float*)d_in[18];
    const float* fb     = (const float*)d_in[19];
    float* out = (float*)d_out;

    k_gather<<<(VV + 255) / 256, 256>>>(srpe, sdist);
    k_rel<<<V, 256>>>();
    k_x3<<<(BT * V + 255) / 256, 256>>>(inputs);
    k_packT<<<dim3(VE2 / 64, 6), 256>>>(t2t);
    k_packW<<<dim3(6, 6, B), 256>>>(inputs, dw1, dw2);
    k_sgemm_y<<<dim3(5, 24), 256>>>();
    k_connect<<<dim3(V, T), 128>>>(inputs, conv_w, conv_b, sape, dow, tod, cw, cb);
    k_packA<<<(B * 384 * 48) / 256, 256>>>();
    k_dyn_mma<<<dim3(6, 3, B), 256>>>(inputs, do1, do2);
    k_tg_mma<<<dim3(3, 12, KSPLIT), 256>>>();
    k_tgr<<<(BT * V + 255) / 256, 256>>>();
    k_gt<<<(B * V) / 8, 256>>>(g2g);
    k_out<<<(B * V + 255) / 256, 256>>>(w1, w2, fw, fb, out);
}

// round 12
// speedup vs baseline: 2.5043x; 1.4227x over previous
#include <cuda_runtime.h>
#include <cuda_bf16.h>
#include <math.h>
#include <stdint.h>

#define V 307
#define T 12
#define E 32
#define B 128
#define NPRE 12
#define TE 384      // T*E
#define N2 768      // 2E*T
#define VE2 19648   // V*2E
#define VV 94249    // V*V
#define BT 1536     // B*T
#define IN_ROW 309
#define IN_B 4017   // 13*309
#define HB 235776   // V*N2 = 12*VE2
#define KSPLIT 4

#define MSTR 72         // smem row stride (bf16) = 144B, conflict-free ldmatrix
#define TILE_B 18432    // 128*MSTR*2 bytes per tile
#define STAGE_B 73728   // 4 tiles per stage
#define QSMEM 147456    // 2 stages

// ---------------- scratch ----------------------------------------------------
__device__ float g_rpe[VV];
__device__ float g_rpeT[VV];
__device__ float g_rel[VV];
__device__ float g_rsum[V];
__device__ float g_x3d[BT * V];
__device__ float g_y[BT * V];
__device__ float g_hA[B * V * TE];           // [b][g][t*E+e]
__device__ float g_hC[(size_t)B * V * N2];   // dyn output plain [b][g][n]
__device__ float g_h3[(size_t)B * HB];       // [b][j][g][i]
__device__ float g_tgp[KSPLIT * BT * V];
__device__ float g_tg[BT * V];
__device__ float g_gt[B * V * NPRE];
// bf16 hi/lo operand images
__device__ unsigned short g_Ahd[(size_t)B * 384 * TE];   // dyn A  [b][row384][k384]
__device__ unsigned short g_Ald[(size_t)B * 384 * TE];
__device__ unsigned short g_Whd[(size_t)B * N2 * TE];    // dyn B' [b][n768][k384]
__device__ unsigned short g_Wld[(size_t)B * N2 * TE];
__device__ unsigned short g_h3h[(size_t)BT * VE2];       // tg A   [bt][k]
__device__ unsigned short g_h3l[(size_t)BT * VE2];
__device__ unsigned short g_Th[(size_t)384 * VE2];       // tg B'  [v384][k]
__device__ unsigned short g_Tl[(size_t)384 * VE2];

__device__ __forceinline__ float leakyf(float x) { return x >= 0.f ? x : 0.3f * x; }

__device__ __forceinline__ uint32_t smem_u32(const void* p) {
    uint32_t a;
    asm("{ .reg .u64 t; cvta.to.shared.u64 t, %1; cvt.u32.u64 %0, t; }" : "=r"(a) : "l"(p));
    return a;
}
__device__ __forceinline__ void ldsm_x4(uint32_t& r0, uint32_t& r1, uint32_t& r2, uint32_t& r3, uint32_t addr) {
    asm volatile("ldmatrix.sync.aligned.m8n8.x4.shared.b16 {%0,%1,%2,%3}, [%4];"
        : "=r"(r0), "=r"(r1), "=r"(r2), "=r"(r3) : "r"(addr));
}
__device__ __forceinline__ void mma16816(float* c, const uint32_t* a, uint32_t b0, uint32_t b1) {
    asm volatile("mma.sync.aligned.m16n8k16.row.col.f32.bf16.bf16.f32 "
        "{%0,%1,%2,%3}, {%4,%5,%6,%7}, {%8,%9}, {%0,%1,%2,%3};"
        : "+f"(c[0]), "+f"(c[1]), "+f"(c[2]), "+f"(c[3])
        : "r"(a[0]), "r"(a[1]), "r"(a[2]), "r"(a[3]), "r"(b0), "r"(b1));
}
__device__ __forceinline__ void bf16split(float x, unsigned short& hb, unsigned short& lb) {
    __nv_bfloat16 h = __float2bfloat16(x);
    float r = x - __bfloat162float(h);
    __nv_bfloat16 l = __float2bfloat16(r);
    hb = *(unsigned short*)&h;
    lb = *(unsigned short*)&l;
}
__device__ __forceinline__ void cpasync16(uint32_t dst, const void* src) {
    asm volatile("cp.async.cg.shared.global [%0], [%1], 16;" :: "r"(dst), "l"(src));
}
#define CP_COMMIT() asm volatile("cp.async.commit_group;" ::: "memory")
#define CP_WAIT(n)  asm volatile("cp.async.wait_group %0;" :: "n"(n) : "memory")

// ---------------- quad mma core: 128x128 tile, BK=64, fused hi/lo 3-pass ----
// smem: 2 stages x {Ah, Al, Bh, Bl} of 128x64 bf16 tiles (MSTR stride).
__device__ __forceinline__ void mma_gemm_quad(
    const unsigned short* __restrict__ Ah, const unsigned short* __restrict__ Al, size_t lda,
    const unsigned short* __restrict__ Bh, const unsigned short* __restrict__ Bl, size_t ldb,
    int m0, int n0, int kbeg, int nch,
    unsigned short* smem, float acc[4][4][4])
{
    int tid = threadIdx.x;
    int lane = tid & 31, wid = tid >> 5;
    int wm = (wid & 1) * 64, wn = (wid >> 1) * 32;
    int seg = tid & 7, rb = tid >> 3;
    uint32_t sbase = smem_u32(smem);

    auto issue = [&](int c) {
        uint32_t sb = sbase + (c & 1) * STAGE_B;
        size_t k0 = (size_t)kbeg + (size_t)c * 64 + seg * 8;
        #pragma unroll
        for (int i = 0; i < 4; i++) {
            int r = rb + 32 * i;
            uint32_t so = (uint32_t)(r * MSTR + seg * 8) * 2;
            cpasync16(sb + so,                Ah + (size_t)(m0 + r) * lda + k0);
            cpasync16(sb + TILE_B + so,       Al + (size_t)(m0 + r) * lda + k0);
            cpasync16(sb + 2 * TILE_B + so,   Bh + (size_t)(n0 + r) * ldb + k0);
            cpasync16(sb + 3 * TILE_B + so,   Bl + (size_t)(n0 + r) * ldb + k0);
        }
        CP_COMMIT();
    };

    issue(0);
    for (int c = 0; c < nch; c++) {
        if (c + 1 < nch) { issue(c + 1); CP_WAIT(1); }
        else             { CP_WAIT(0); }
        __syncthreads();
        uint32_t sb = sbase + (c & 1) * STAGE_B;
        #pragma unroll
        for (int k16 = 0; k16 < 4; k16++) {
            uint32_t ah[4][4], al[4][4], bh[2][4], bl[2][4];
            uint32_t acol = (uint32_t)(k16 * 16 + (lane >> 4) * 8) * 2;
            #pragma unroll
            for (int mi = 0; mi < 4; mi++) {
                uint32_t ao = sb + (uint32_t)(wm + mi * 16 + (lane & 15)) * (MSTR * 2) + acol;
                ldsm_x4(ah[mi][0], ah[mi][1], ah[mi][2], ah[mi][3], ao);
                ldsm_x4(al[mi][0], al[mi][1], al[mi][2], al[mi][3], ao + TILE_B);
            }
            uint32_t brow = (lane & 7) + (lane >> 4) * 8;
            uint32_t bcol = (uint32_t)(k16 * 16 + ((lane >> 3) & 1) * 8) * 2;
            #pragma unroll
            for (int nj = 0; nj < 2; nj++) {
                uint32_t bo = sb + (uint32_t)(wn + nj * 16 + brow) * (MSTR * 2) + bcol;
                ldsm_x4(bh[nj][0], bh[nj][1], bh[nj][2], bh[nj][3], bo + 2 * TILE_B);
                ldsm_x4(bl[nj][0], bl[nj][1], bl[nj][2], bl[nj][3], bo + 3 * TILE_B);
            }
            #pragma unroll
            for (int mi = 0; mi < 4; mi++)
                #pragma unroll
                for (int ni = 0; ni < 4; ni++) {
                    uint32_t b0h = bh[ni >> 1][(ni & 1) * 2], b1h = bh[ni >> 1][(ni & 1) * 2 + 1];
                    uint32_t b0l = bl[ni >> 1][(ni & 1) * 2], b1l = bl[ni >> 1][(ni & 1) * 2 + 1];
                    mma16816(acc[mi][ni], ah[mi], b0h, b1h);
                    mma16816(acc[mi][ni], al[mi], b0h, b1h);
                    mma16816(acc[mi][ni], ah[mi], b0l, b1l);
                }
        }
        __syncthreads();
    }
}

// ---------------- K0a: gather rpe + transpose -------------------------------
__global__ void k_gather(const float* __restrict__ srpe, const int* __restrict__ sdist) {
    int i = blockIdx.x * 256 + threadIdx.x;
    if (i < VV) {
        float v = srpe[sdist[i]];
        g_rpe[i] = v;
        g_rpeT[(i % V) * V + (i / V)] = v;
    }
}

// ---------------- K0b: rel = relu(rpe @ rpe^T), rowsum ----------------------
__global__ void k_rel() {
    __shared__ float s[V];
    __shared__ float red[256];
    int v = blockIdx.x;
    for (int k = threadIdx.x; k < V; k += 256) s[k] = g_rpe[v * V + k];
    __syncthreads();
    float lr = 0.f;
    for (int g = threadIdx.x; g < V; g += 256) {
        float sum = 0.f;
        for (int k = 0; k < V; k++) sum += s[k] * g_rpeT[k * V + g];
        float r = sum > 0.f ? sum : 0.f;
        g_rel[v * V + g] = r;
        lr += r;
    }
    red[threadIdx.x] = lr;
    __syncthreads();
    for (int st = 128; st > 0; st >>= 1) {
        if (threadIdx.x < st) red[threadIdx.x] += red[threadIdx.x + st];
        __syncthreads();
    }
    if (threadIdx.x == 0) g_rsum[v] = red[0];
}

// ---------------- K1x: extract dense x3 [bt][v] -----------------------------
__global__ void k_x3(const float* __restrict__ inp) {
    int idx = blockIdx.x * 256 + threadIdx.x;
    if (idx >= BT * V) return;
    int bt = idx / V, v = idx % V;
    int b = bt / T, t = bt % T;
    g_x3d[idx] = inp[b * IN_B + (1 + t) * IN_ROW + 2 + v];
}

// ---------------- small SGEMM tile core (64x64, BK=16) ----------------------
__device__ __forceinline__ void gemm_tile(
    const float* __restrict__ A, int lda, int M,
    const float* __restrict__ Bm, int ldb, int N,
    int m0, int n0, int kbeg, int kend, float acc[4][4])
{
    __shared__ float sA[16 * 64];
    __shared__ float sB[16 * 64];
    int tid = threadIdx.x;
    int tm = (tid >> 4) << 2;
    int tn = (tid & 15) << 2;
    for (int k0 = kbeg; k0 < kend; k0 += 16) {
        #pragma unroll
        for (int i = 0; i < 4; i++) {
            int idx = tid + i * 256;
            int m = idx >> 4;
            int kk = idx & 15;
            int gm = m0 + m, gk = k0 + kk;
            float v = (gm < M && gk < kend) ? A[(size_t)gm * lda + gk] : 0.f;
            sA[kk * 64 + m] = v;
        }
        #pragma unroll
        for (int i = 0; i < 4; i++) {
            int idx = tid + i * 256;
            int kk = idx >> 6;
            int n = idx & 63;
            int gk = k0 + kk, gn = n0 + n;
            float v = (gk < kend && gn < N) ? Bm[(size_t)gk * ldb + gn] : 0.f;
            sB[kk * 64 + n] = v;
        }
        __syncthreads();
        #pragma unroll
        for (int kk = 0; kk < 16; kk++) {
            float4 a4 = *(const float4*)(sA + kk * 64 + tm);
            float4 b4 = *(const float4*)(sB + kk * 64 + tn);
            float av[4] = {a4.x, a4.y, a4.z, a4.w};
            float bv[4] = {b4.x, b4.y, b4.z, b4.w};
            #pragma unroll
            for (int x = 0; x < 4; x++)
                #pragma unroll
                for (int y = 0; y < 4; y++)
                    acc[x][y] += av[x] * bv[y];
        }
        __syncthreads();
    }
}

// ---------------- K1: y = X3 (1536x307) @ rel (307x307) ---------------------
__global__ void k_sgemm_y() {
    float acc[4][4] = {};
    int m0 = blockIdx.y * 64, n0 = blockIdx.x * 64;
    gemm_tile(g_x3d, V, BT, g_rel, V, V, m0, n0, 0, V, acc);
    int tid = threadIdx.x;
    int tm = (tid >> 4) << 2, tn = (tid & 15) << 2;
    #pragma unroll
    for (int x = 0; x < 4; x++) {
        int m = m0 + tm + x;
        if (m >= BT) continue;
        #pragma unroll
        for (int y = 0; y < 4; y++) {
            int n = n0 + tn + y;
            if (n < V) g_y[m * V + n] = acc[x][y];
        }
    }
}

// ---------------- K2: connect layer ------------------------------------------
__global__ void __launch_bounds__(128) k_connect(
    const float* __restrict__ inp,
    const float* __restrict__ conv_w, const float* __restrict__ conv_b,
    const float* __restrict__ sape, const float* __restrict__ dow,
    const float* __restrict__ tod,
    const float* __restrict__ cw, const float* __restrict__ cb)
{
    int v = blockIdx.x, t = blockIdx.y;
    __shared__ float s_cw[96 * 32];
    __shared__ float s_cb[32], s_w[32], s_b[32];
    const float* cwp = cw + (size_t)(t * V + v) * 96 * 32;
    for (int i = threadIdx.x; i < 3072; i += 128) s_cw[i] = cwp[i];
    if (threadIdx.x < 32) {
        s_cb[threadIdx.x] = cb[(t * V + v) * 32 + threadIdx.x];
        s_w[threadIdx.x] = conv_w[threadIdx.x];
        s_b[threadIdx.x] = conv_b[threadIdx.x];
    }
    __syncthreads();
    int b = threadIdx.x;
    float yv = g_y[(b * T + t) * V + v];
    float rv = g_rsum[v];
    int nr = (int)inp[b * IN_B + 2 + v];
    int sw = (int)inp[b * IN_B + (1 + t) * IN_ROW + 0];
    int sd = (int)inp[b * IN_B + (1 + t) * IN_ROW + 1];
    const float* sp = sape + (nr * T + t) * E;
    const float* dwp = dow + (sw * V + v) * E;
    const float* tdp = tod + (sd * V + v) * E;

    float acc[32];
    #pragma unroll
    for (int e = 0; e < 32; e++) acc[e] = s_cb[e];

    #pragma unroll
    for (int f = 0; f < 32; f++) {
        float xf = yv * s_w[f] + rv * s_b[f];
        const float4* c4 = (const float4*)(s_cw + f * 32);
        #pragma unroll
        for (int e4 = 0; e4 < 8; e4++) {
            float4 w4 = c4[e4];
            acc[e4 * 4 + 0] += xf * w4.x; acc[e4 * 4 + 1] += xf * w4.y;
            acc[e4 * 4 + 2] += xf * w4.z; acc[e4 * 4 + 3] += xf * w4.w;
        }
    }
    #pragma unroll
    for (int f = 0; f < 32; f++) {
        float xf = sp[f];
        const float4* c4 = (const float4*)(s_cw + (32 + f) * 32);
        #pragma unroll
        for (int e4 = 0; e4 < 8; e4++) {
            float4 w4 = c4[e4];
            acc[e4 * 4 + 0] += xf * w4.x; acc[e4 * 4 + 1] += xf * w4.y;
            acc[e4 * 4 + 2] += xf * w4.z; acc[e4 * 4 + 3] += xf * w4.w;
        }
    }
    #pragma unroll
    for (int f = 0; f < 32; f++) {
        float xf = dwp[f] + tdp[f];
        const float4* c4 = (const float4*)(s_cw + (64 + f) * 32);
        #pragma unroll
        for (int e4 = 0; e4 < 8; e4++) {
            float4 w4 = c4[e4];
            acc[e4 * 4 + 0] += xf * w4.x; acc[e4 * 4 + 1] += xf * w4.y;
            acc[e4 * 4 + 2] += xf * w4.z; acc[e4 * 4 + 3] += xf * w4.w;
        }
    }
    float* o = g_hA + (size_t)(b * V + v) * TE + t * E;
    #pragma unroll
    for (int e = 0; e < 32; e++) o[e] = leakyf(acc[e]);
}

// ---------------- pack: hA -> dyn A images (pad rows to 384) -----------------
__global__ void __launch_bounds__(256) k_packA() {
    int idx = blockIdx.x * 256 + threadIdx.x;
    if (idx >= B * 384 * 48) return;
    int seg = idx % 48;
    int rem = idx / 48;
    int row = rem % 384;
    int b = rem / 384;
    union { unsigned short u[8]; uint4 v; } ph, pl;
    if (row < V) {
        const float* src = g_hA + ((size_t)b * V + row) * TE + seg * 8;
        #pragma unroll
        for (int j = 0; j < 8; j++) bf16split(src[j], ph.u[j], pl.u[j]);
    } else {
        ph.v = make_uint4(0, 0, 0, 0);
        pl.v = make_uint4(0, 0, 0, 0);
    }
    size_t o = ((size_t)b * 384 + row) * TE + seg * 8;
    *(uint4*)(g_Ahd + o) = ph.v;
    *(uint4*)(g_Ald + o) = pl.v;
}

// ---------------- pack: Wsum = W1[wk]+W2[dt], transposed to [n][k] -----------
__global__ void __launch_bounds__(256) k_packW(
    const float* __restrict__ inp,
    const float* __restrict__ w1all, const float* __restrict__ w2all)
{
    __shared__ float s[64 * 129];
    int nt = blockIdx.x, kc = blockIdx.y, b = blockIdx.z;
    int n0 = nt * 128, k0 = kc * 64;
    int wk = (int)inp[b * IN_B + 0];
    int dt = (int)inp[b * IN_B + 1];
    const float* w1p = w1all + (size_t)wk * TE * N2;
    const float* w2p = w2all + (size_t)dt * TE * N2;
    for (int idx = threadIdx.x; idx < 8192; idx += 256) {
        int k = idx >> 7, n = idx & 127;
        size_t g = (size_t)(k0 + k) * N2 + n0 + n;
        s[k * 129 + n] = w1p[g] + w2p[g];
    }
    __syncthreads();
    for (int t2 = threadIdx.x; t2 < 1024; t2 += 256) {
        int n = t2 >> 3, seg = t2 & 7;
        union { unsigned short u[8]; uint4 v; } ph, pl;
        #pragma unroll
        for (int j = 0; j < 8; j++) bf16split(s[(seg * 8 + j) * 129 + n], ph.u[j], pl.u[j]);
        size_t o = ((size_t)b * N2 + n0 + n) * TE + k0 + seg * 8;
        *(uint4*)(g_Whd + o) = ph.v;
        *(uint4*)(g_Wld + o) = pl.v;
    }
}

// ---------------- pack: tge2tg transpose -> [v 384][k 19648] hi/lo -----------
__global__ void __launch_bounds__(256) k_packT(const float* __restrict__ t2t) {
    __shared__ float s[64][65];
    int kc = blockIdx.x, nc = blockIdx.y;
    int k0 = kc * 64, n0 = nc * 64;
    for (int idx = threadIdx.x; idx < 4096; idx += 256) {
        int k = idx >> 6, n = idx & 63;
        s[k][n] = (n0 + n < V) ? t2t[(size_t)(k0 + k) * V + n0 + n] : 0.f;
    }
    __syncthreads();
    for (int t2 = threadIdx.x; t2 < 512; t2 += 256) {
        int n = t2 >> 3, seg = t2 & 7;
        union { unsigned short u[8]; uint4 v; } ph, pl;
        #pragma unroll
        for (int j = 0; j < 8; j++) bf16split(s[seg * 8 + j][n], ph.u[j], pl.u[j]);
        size_t o = (size_t)(n0 + n) * VE2 + k0 + seg * 8;
        *(uint4*)(g_Th + o) = ph.v;
        *(uint4*)(g_Tl + o) = pl.v;
    }
}

// ---------------- K3: dynamic layer via quad mma core ------------------------
// grid (6 nt, 3 mt, B); writes plain [b][g][n] fp32 (coalesced)
__global__ void __launch_bounds__(256, 1) k_dyn_mma(
    const float* __restrict__ inp,
    const float* __restrict__ o1all, const float* __restrict__ o2all)
{
    extern __shared__ unsigned short qsm[];
    int nt = blockIdx.x, mt = blockIdx.y, b = blockIdx.z;
    int m0 = mt * 128, n0 = nt * 128;
    float acc[4][4][4];
    #pragma unroll
    for (int i = 0; i < 4; i++)
        #pragma unroll
        for (int j = 0; j < 4; j++)
            #pragma unroll
            for (int r = 0; r < 4; r++) acc[i][j][r] = 0.f;

    mma_gemm_quad(g_Ahd + (size_t)b * 384 * TE, g_Ald + (size_t)b * 384 * TE, TE,
                  g_Whd + (size_t)b * N2 * TE,  g_Wld + (size_t)b * N2 * TE,  TE,
                  m0, n0, 0, TE / 64, qsm, acc);

    int tid = threadIdx.x, lane = tid & 31, wid = tid >> 5;
    int wm = (wid & 1) * 64, wn = (wid >> 1) * 32;
    int gr = lane >> 2, tc = (lane & 3) * 2;
    int wk = (int)inp[b * IN_B + 0];
    int dt = (int)inp[b * IN_B + 1];
    const float* b1 = o1all + (size_t)wk * HB;
    const float* b2 = o2all + (size_t)dt * HB;
    float* hc = g_hC + (size_t)b * V * N2;
    #pragma unroll
    for (int mi = 0; mi < 4; mi++) {
        #pragma unroll
        for (int h = 0; h < 2; h++) {
            int g = m0 + wm + mi * 16 + gr + h * 8;
            if (g >= V) continue;
            #pragma unroll
            for (int ni = 0; ni < 4; ni++) {
                #pragma unroll
                for (int cb = 0; cb < 2; cb++) {
                    int n = n0 + wn + ni * 8 + tc + cb;
                    float val = 0.5f * (acc[mi][ni][h * 2 + cb] + b1[g * N2 + n] + b2[g * N2 + n]);
                    hc[(size_t)g * N2 + n] = leakyf(val);
                }
            }
        }
    }
}

// ---------------- K3b: transpose hC -> h3 (fp32) + bf16 hi/lo images ---------
// grid (39, B): each block handles 8 g-rows of one batch.
__global__ void __launch_bounds__(256) k_h3t() {
    __shared__ float s[8][768];
    int b = blockIdx.y, g0 = blockIdx.x * 8;
    for (int idx = threadIdx.x; idx < 8 * 768; idx += 256) {
        int r = idx / 768, n = idx % 768;
        int g = g0 + r;
        s[r][n] = (g < V) ? g_hC[(size_t)b * V * N2 + (size_t)g * N2 + n] : 0.f;
    }
    __syncthreads();
    for (int task = threadIdx.x; task < 12 * 8 * 16; task += 256) {
        int i4 = task & 15;
        int r = (task >> 4) & 7;
        int j = task >> 7;
        int g = g0 + r;
        if (g >= V) continue;
        float v[4];
        union { unsigned short u[4]; uint2 w; } hh, ll;
        #pragma unroll
        for (int q = 0; q < 4; q++) {
            int i = i4 * 4 + q;
            v[q] = s[r][i * 12 + j];
            bf16split(v[q], hh.u[q], ll.u[q]);
        }
        size_t o = (size_t)b * HB + (size_t)j * VE2 + (size_t)g * 64 + i4 * 4;
        *(float4*)(g_h3 + o) = make_float4(v[0], v[1], v[2], v[3]);
        size_t o2 = (size_t)(b * 12 + j) * VE2 + (size_t)g * 64 + i4 * 4;
        *(uint2*)(g_h3h + o2) = hh.w;
        *(uint2*)(g_h3l + o2) = ll.w;
    }
}

// ---------------- K4: tg via quad mma core, split-K --------------------------
// grid (3 nt, 12 mt, KSPLIT)
__global__ void __launch_bounds__(256, 1) k_tg_mma() {
    extern __shared__ unsigned short qsm[];
    int nt = blockIdx.x, mt = blockIdx.y, ks = blockIdx.z;
    int m0 = mt * 128, n0 = nt * 128;
    int c0 = (ks * 307) / KSPLIT, c1 = ((ks + 1) * 307) / KSPLIT;
    float acc[4][4][4];
    #pragma unroll
    for (int i = 0; i < 4; i++)
        #pragma unroll
        for (int j = 0; j < 4; j++)
            #pragma unroll
            for (int r = 0; r < 4; r++) acc[i][j][r] = 0.f;

    mma_gemm_quad(g_h3h, g_h3l, VE2, g_Th, g_Tl, VE2, m0, n0, c0 * 64, c1 - c0, qsm, acc);

    int tid = threadIdx.x, lane = tid & 31, wid = tid >> 5;
    int wm = (wid & 1) * 64, wn = (wid >> 1) * 32;
    int gr = lane >> 2, tc = (lane & 3) * 2;
    float* pp = g_tgp + (size_t)ks * BT * V;
    #pragma unroll
    for (int mi = 0; mi < 4; mi++) {
        #pragma unroll
        for (int h = 0; h < 2; h++) {
            int m = m0 + wm + mi * 16 + gr + h * 8;
            #pragma unroll
            for (int ni = 0; ni < 4; ni++) {
                #pragma unroll
                for (int cb = 0; cb < 2; cb++) {
                    int n = n0 + wn + ni * 8 + tc + cb;
                    if (n < V) pp[(size_t)m * V + n] = acc[mi][ni][h * 2 + cb];
                }
            }
        }
    }
}

__global__ void k_tgr() {
    int i = blockIdx.x * 256 + threadIdx.x;
    if (i < BT * V) {
        float s = 0.f;
        #pragma unroll
        for (int k = 0; k < KSPLIT; k++) s += g_tgp[(size_t)k * BT * V + i];
        g_tg[i] = s;
    }
}

// ---------------- K5: gt = rows(H3 as (B*V)x768) @ gte2gt(768x12) -----------
__global__ void k_gt(const float* __restrict__ g2g) {
    __shared__ float s[N2 * NPRE];
    for (int i = threadIdx.x; i < N2 * NPRE; i += 256) s[i] = g2g[i];
    __syncthreads();
    int wid = threadIdx.x >> 5, lane = threadIdx.x & 31;
    int r = blockIdx.x * 8 + wid;
    const float* row = g_h3 + (size_t)r * N2;
    float acc[NPRE] = {};
    for (int m = lane; m < N2; m += 32) {
        float a = row[m];
        const float* sm = s + m * NPRE;
        #pragma unroll
        for (int o = 0; o < NPRE; o++) acc[o] += a * sm[o];
    }
    #pragma unroll
    for (int o = 0; o < NPRE; o++) {
        #pragma unroll
        for (int st = 16; st > 0; st >>= 1)
            acc[o] += __shfl_xor_sync(0xffffffffu, acc[o], st);
    }
    if (lane == 0) {
        #pragma unroll
        for (int o = 0; o < NPRE; o++) g_gt[r * NPRE + o] = acc[o];
    }
}

// ---------------- K6: gates + weight1/2 + fully -----------------------------
__global__ void k_out(const float* __restrict__ w1, const float* __restrict__ w2,
                      const float* __restrict__ fw, const float* __restrict__ fb,
                      float* __restrict__ out)
{
    int idx = blockIdx.x * 256 + threadIdx.x;
    if (idx >= B * V) return;
    int b = idx / V, g = idx % V;
    float gt1[T], gt2[T];
    #pragma unroll
    for (int t = 0; t < T; t++) {
        float x3v = g_x3d[(b * T + t) * V + g];
        float tgv = g_tg[(b * T + t) * V + g];
        float gtv = g_gt[idx * NPRE + t];
        gt1[t] = (tgv + x3v) * (1.f / (1.f + expf(-tgv)));
        gt2[t] = (gtv + x3v) * (1.f / (1.f + expf(-gtv)));
    }
    float x1[NPRE], x2[NPRE];
    #pragma unroll
    for (int o = 0; o < NPRE; o++) { x1[o] = 0.f; x2[o] = 0.f; }
    #pragma unroll
    for (int i = 0; i < T; i++) {
        float a = gt1[i], c = gt2[i];
        #pragma unroll
        for (int o = 0; o < NPRE; o++) {
            x1[o] += w1[g * 144 + i * 12 + o] * a;
            x2[o] += w2[g * 144 + i * 12 + o] * c;
        }
    }
    #pragma unroll
    for (int o = 0; o < NPRE; o++) {
        float sacc = fb[o];
        #pragma unroll
        for (int i = 0; i < NPRE; i++) {
            sacc += x1[i] * fw[i * 12 + o] + x2[i] * fw[(12 + i) * 12 + o];
        }
        out[(size_t)b * NPRE * V + o * V + g] = sacc;
    }
}

// ---------------- launch -----------------------------------------------------
extern "C" void kernel_launch(void* const* d_in, const int* in_sizes, int n_in,
                              void* d_out, int out_size) {
    const float* inputs = (const float*)d_in[0];
    const int*   sdist  = (const int*)d_in[1];
    const float* conv_w = (const float*)d_in[2];
    const float* conv_b = (const float*)d_in[3];
    const float* srpe   = (const float*)d_in[4];
    const float* sape   = (const float*)d_in[5];
    const float* dow    = (const float*)d_in[6];
    const float* tod    = (const float*)d_in[7];
    const float* cw     = (const float*)d_in[8];
    const float* cb     = (const float*)d_in[9];
    const float* dw1    = (const float*)d_in[10];
    const float* do1    = (const float*)d_in[11];
    const float* dw2    = (const float*)d_in[12];
    const float* do2    = (const float*)d_in[13];
    const float* t2t    = (const float*)d_in[14];
    const float* g2g    = (const float*)d_in[15];
    const float* w1     = (const float*)d_in[16];
    const float* w2     = (const float*)d_in[17];
    const float* fw     = (const float*)d_in[18];
    const float* fb     = (const float*)d_in[19];
    float* out = (float*)d_out;

    cudaFuncSetAttribute(k_dyn_mma, cudaFuncAttributeMaxDynamicSharedMemorySize, QSMEM);
    cudaFuncSetAttribute(k_tg_mma, cudaFuncAttributeMaxDynamicSharedMemorySize, QSMEM);

    k_gather<<<(VV + 255) / 256, 256>>>(srpe, sdist);
    k_rel<<<V, 256>>>();
    k_x3<<<(BT * V + 255) / 256, 256>>>(inputs);
    k_packT<<<dim3(VE2 / 64, 6), 256>>>(t2t);
    k_packW<<<dim3(6, 6, B), 256>>>(inputs, dw1, dw2);
    k_sgemm_y<<<dim3(5, 24), 256>>>();
    k_connect<<<dim3(V, T), 128>>>(inputs, conv_w, conv_b, sape, dow, tod, cw, cb);
    k_packA<<<(B * 384 * 48) / 256, 256>>>();
    k_dyn_mma<<<dim3(6, 3, B), 256, QSMEM>>>(inputs, do1, do2);
    k_h3t<<<dim3(39, B), 256>>>();
    k_tg_mma<<<dim3(3, 12, KSPLIT), 256, QSMEM>>>();
    k_tgr<<<(BT * V + 255) / 256, 256>>>();
    k_gt<<<(B * V) / 8, 256>>>(g2g);
    k_out<<<(B * V + 255) / 256, 256>>>(w1, w2, fw, fb, out);
}

// round 15
// speedup vs baseline: 2.6696x; 1.0660x over previous
#include <cuda_runtime.h>
#include <cuda_bf16.h>
#include <math.h>
#include <stdint.h>

#define V 307
#define T 12
#define E 32
#define B 128
#define NPRE 12
#define TE 384      // T*E
#define N2 768      // 2E*T
#define VE2 19648   // V*2E
#define VV 94249    // V*V
#define BT 1536     // B*T
#define IN_ROW 309
#define IN_B 4017   // 13*309
#define HB 235776   // V*N2 = 12*VE2
#define KSPLIT 4

#define MSTR 72         // smem row stride (bf16) = 144B, conflict-free ldmatrix
#define TILE_B 18432    // 128*MSTR*2 bytes per tile
#define STAGE_B 73728   // 4 tiles per stage
#define QSMEM 221184    // 3 stages

// ---------------- scratch ----------------------------------------------------
__device__ float g_rpe[VV];
__device__ float g_rpeT[VV];
__device__ float g_rel[VV];
__device__ float g_rsum[V];
__device__ float g_x3d[BT * V];
__device__ float g_y[BT * V];
__device__ float g_hC[(size_t)B * V * N2];   // dyn output plain [b][g][n]
__device__ float g_tgp[KSPLIT * BT * V];
__device__ float g_gt[B * V * NPRE];
// bf16 hi/lo operand images
__device__ unsigned short g_Ahd[(size_t)B * 384 * TE];   // dyn A  [b][row384][k384]
__device__ unsigned short g_Ald[(size_t)B * 384 * TE];
__device__ unsigned short g_Whd[(size_t)B * N2 * TE];    // dyn B' [b][n768][k384]
__device__ unsigned short g_Wld[(size_t)B * N2 * TE];
__device__ unsigned short g_h3h[(size_t)BT * VE2];       // tg A [bt][k]; flat [b][HB] = h3 rows
__device__ unsigned short g_h3l[(size_t)BT * VE2];
__device__ unsigned short g_Th[(size_t)384 * VE2];       // tg B'  [v384][k]
__device__ unsigned short g_Tl[(size_t)384 * VE2];

__device__ __forceinline__ float leakyf(float x) { return x >= 0.f ? x : 0.3f * x; }

__device__ __forceinline__ uint32_t smem_u32(const void* p) {
    uint32_t a;
    asm("{ .reg .u64 t; cvta.to.shared.u64 t, %1; cvt.u32.u64 %0, t; }" : "=r"(a) : "l"(p));
    return a;
}
__device__ __forceinline__ void ldsm_x4(uint32_t& r0, uint32_t& r1, uint32_t& r2, uint32_t& r3, uint32_t addr) {
    asm volatile("ldmatrix.sync.aligned.m8n8.x4.shared.b16 {%0,%1,%2,%3}, [%4];"
        : "=r"(r0), "=r"(r1), "=r"(r2), "=r"(r3) : "r"(addr));
}
__device__ __forceinline__ void mma16816(float* c, const uint32_t* a, uint32_t b0, uint32_t b1) {
    asm volatile("mma.sync.aligned.m16n8k16.row.col.f32.bf16.bf16.f32 "
        "{%0,%1,%2,%3}, {%4,%5,%6,%7}, {%8,%9}, {%0,%1,%2,%3};"
        : "+f"(c[0]), "+f"(c[1]), "+f"(c[2]), "+f"(c[3])
        : "r"(a[0]), "r"(a[1]), "r"(a[2]), "r"(a[3]), "r"(b0), "r"(b1));
}
__device__ __forceinline__ void bf16split(float x, unsigned short& hb, unsigned short& lb) {
    __nv_bfloat16 h = __float2bfloat16(x);
    float r = x - __bfloat162float(h);
    __nv_bfloat16 l = __float2bfloat16(r);
    hb = *(unsigned short*)&h;
    lb = *(unsigned short*)&l;
}
__device__ __forceinline__ float bf16join(unsigned short hb, unsigned short lb) {
    return __bfloat162float(*(__nv_bfloat16*)&hb) + __bfloat162float(*(__nv_bfloat16*)&lb);
}
__device__ __forceinline__ void cpasync16(uint32_t dst, const void* src) {
    asm volatile("cp.async.cg.shared.global [%0], [%1], 16;" :: "r"(dst), "l"(src));
}
#define CP_COMMIT() asm volatile("cp.async.commit_group;" ::: "memory")
#define CP_WAIT(n)  asm volatile("cp.async.wait_group %0;" :: "n"(n) : "memory")

// ---------------- quad mma core: 128x128 tile, BK=64, 3-stage, hi/lo 3-pass --
__device__ __forceinline__ void mma_gemm_quad(
    const unsigned short* __restrict__ Ah, const unsigned short* __restrict__ Al, size_t lda,
    const unsigned short* __restrict__ Bh, const unsigned short* __restrict__ Bl, size_t ldb,
    int m0, int n0, int kbeg, int nch,
    unsigned short* smem, float acc[4][4][4])
{
    int tid = threadIdx.x;
    int lane = tid & 31, wid = tid >> 5;
    int wm = (wid & 1) * 64, wn = (wid >> 1) * 32;
    int seg = tid & 7, rb = tid >> 3;
    uint32_t sbase = smem_u32(smem);

    auto issue = [&](int c) {
        uint32_t sb = sbase + (uint32_t)(c % 3) * STAGE_B;
        size_t k0 = (size_t)kbeg + (size_t)c * 64 + seg * 8;
        #pragma unroll
        for (int i = 0; i < 4; i++) {
            int r = rb + 32 * i;
            uint32_t so = (uint32_t)(r * MSTR + seg * 8) * 2;
            cpasync16(sb + so,                Ah + (size_t)(m0 + r) * lda + k0);
            cpasync16(sb + TILE_B + so,       Al + (size_t)(m0 + r) * lda + k0);
            cpasync16(sb + 2 * TILE_B + so,   Bh + (size_t)(n0 + r) * ldb + k0);
            cpasync16(sb + 3 * TILE_B + so,   Bl + (size_t)(n0 + r) * ldb + k0);
        }
        CP_COMMIT();
    };

    issue(0);
    if (nch > 1) issue(1);
    for (int c = 0; c < nch; c++) {
        if (c + 2 <= nch) { CP_WAIT(1); } else { CP_WAIT(0); }
        __syncthreads();
        if (c + 2 < nch) issue(c + 2);
        uint32_t sb = sbase + (uint32_t)(c % 3) * STAGE_B;
        #pragma unroll
        for (int k16 = 0; k16 < 4; k16++) {
            uint32_t ah[4][4], al[4][4], bh[2][4], bl[2][4];
            uint32_t acol = (uint32_t)(k16 * 16 + (lane >> 4) * 8) * 2;
            #pragma unroll
            for (int mi = 0; mi < 4; mi++) {
                uint32_t ao = sb + (uint32_t)(wm + mi * 16 + (lane & 15)) * (MSTR * 2) + acol;
                ldsm_x4(ah[mi][0], ah[mi][1], ah[mi][2], ah[mi][3], ao);
                ldsm_x4(al[mi][0], al[mi][1], al[mi][2], al[mi][3], ao + TILE_B);
            }
            uint32_t brow = (lane & 7) + (lane >> 4) * 8;
            uint32_t bcol = (uint32_t)(k16 * 16 + ((lane >> 3) & 1) * 8) * 2;
            #pragma unroll
            for (int nj = 0; nj < 2; nj++) {
                uint32_t bo = sb + (uint32_t)(wn + nj * 16 + brow) * (MSTR * 2) + bcol;
                ldsm_x4(bh[nj][0], bh[nj][1], bh[nj][2], bh[nj][3], bo + 2 * TILE_B);
                ldsm_x4(bl[nj][0], bl[nj][1], bl[nj][2], bl[nj][3], bo + 3 * TILE_B);
            }
            #pragma unroll
            for (int mi = 0; mi < 4; mi++)
                #pragma unroll
                for (int ni = 0; ni < 4; ni++) {
                    uint32_t b0h = bh[ni >> 1][(ni & 1) * 2], b1h = bh[ni >> 1][(ni & 1) * 2 + 1];
                    uint32_t b0l = bl[ni >> 1][(ni & 1) * 2], b1l = bl[ni >> 1][(ni & 1) * 2 + 1];
                    mma16816(acc[mi][ni], ah[mi], b0h, b1h);
                    mma16816(acc[mi][ni], al[mi], b0h, b1h);
                    mma16816(acc[mi][ni], ah[mi], b0l, b1l);
                }
        }
    }
    __syncthreads();
}

// ---------------- K0a: gather rpe + transpose -------------------------------
__global__ void k_gather(const float* __restrict__ srpe, const int* __restrict__ sdist) {
    int i = blockIdx.x * 256 + threadIdx.x;
    if (i < VV) {
        float v = srpe[sdist[i]];
        g_rpe[i] = v;
        g_rpeT[(i % V) * V + (i / V)] = v;
    }
}

// ---------------- K0b: rel = relu(rpe @ rpe^T), rowsum ----------------------
__global__ void k_rel() {
    __shared__ float s[V];
    __shared__ float red[256];
    int v = blockIdx.x;
    for (int k = threadIdx.x; k < V; k += 256) s[k] = g_rpe[v * V + k];
    __syncthreads();
    float lr = 0.f;
    for (int g = threadIdx.x; g < V; g += 256) {
        float sum = 0.f;
        for (int k = 0; k < V; k++) sum += s[k] * g_rpeT[k * V + g];
        float r = sum > 0.f ? sum : 0.f;
        g_rel[v * V + g] = r;
        lr += r;
    }
    red[threadIdx.x] = lr;
    __syncthreads();
    for (int st = 128; st > 0; st >>= 1) {
        if (threadIdx.x < st) red[threadIdx.x] += red[threadIdx.x + st];
        __syncthreads();
    }
    if (threadIdx.x == 0) g_rsum[v] = red[0];
}

// ---------------- K1x: extract dense x3 [bt][v] -----------------------------
__global__ void k_x3(const float* __restrict__ inp) {
    int idx = blockIdx.x * 256 + threadIdx.x;
    if (idx >= BT * V) return;
    int bt = idx / V, v = idx % V;
    int b = bt / T, t = bt % T;
    g_x3d[idx] = inp[b * IN_B + (1 + t) * IN_ROW + 2 + v];
}

// ---------------- small SGEMM tile core (64x64, BK=16) ----------------------
__device__ __forceinline__ void gemm_tile(
    const float* __restrict__ A, int lda, int M,
    const float* __restrict__ Bm, int ldb, int N,
    int m0, int n0, int kbeg, int kend, float acc[4][4])
{
    __shared__ float sA[16 * 64];
    __shared__ float sB[16 * 64];
    int tid = threadIdx.x;
    int tm = (tid >> 4) << 2;
    int tn = (tid & 15) << 2;
    for (int k0 = kbeg; k0 < kend; k0 += 16) {
        #pragma unroll
        for (int i = 0; i < 4; i++) {
            int idx = tid + i * 256;
            int m = idx >> 4;
            int kk = idx & 15;
            int gm = m0 + m, gk = k0 + kk;
            float v = (gm < M && gk < kend) ? A[(size_t)gm * lda + gk] : 0.f;
            sA[kk * 64 + m] = v;
        }
        #pragma unroll
        for (int i = 0; i < 4; i++) {
            int idx = tid + i * 256;
            int kk = idx >> 6;
            int n = idx & 63;
            int gk = k0 + kk, gn = n0 + n;
            float v = (gk < kend && gn < N) ? Bm[(size_t)gk * ldb + gn] : 0.f;
            sB[kk * 64 + n] = v;
        }
        __syncthreads();
        #pragma unroll
        for (int kk = 0; kk < 16; kk++) {
            float4 a4 = *(const float4*)(sA + kk * 64 + tm);
            float4 b4 = *(const float4*)(sB + kk * 64 + tn);
            float av[4] = {a4.x, a4.y, a4.z, a4.w};
            float bv[4] = {b4.x, b4.y, b4.z, b4.w};
            #pragma unroll
            for (int x = 0; x < 4; x++)
                #pragma unroll
                for (int y = 0; y < 4; y++)
                    acc[x][y] += av[x] * bv[y];
        }
        __syncthreads();
    }
}

// ---------------- K1: y = X3 (1536x307) @ rel (307x307) ---------------------
__global__ void k_sgemm_y() {
    float acc[4][4] = {};
    int m0 = blockIdx.y * 64, n0 = blockIdx.x * 64;
    gemm_tile(g_x3d, V, BT, g_rel, V, V, m0, n0, 0, V, acc);
    int tid = threadIdx.x;
    int tm = (tid >> 4) << 2, tn = (tid & 15) << 2;
    #pragma unroll
    for (int x = 0; x < 4; x++) {
        int m = m0 + tm + x;
        if (m >= BT) continue;
        #pragma unroll
        for (int y = 0; y < 4; y++) {
            int n = n0 + tn + y;
            if (n < V) g_y[m * V + n] = acc[x][y];
        }
    }
}

// ---------------- K2: connect layer; writes bf16 hi/lo A-images directly ----
__global__ void __launch_bounds__(128) k_connect(
    const float* __restrict__ inp,
    const float* __restrict__ conv_w, const float* __restrict__ conv_b,
    const float* __restrict__ sape, const float* __restrict__ dow,
    const float* __restrict__ tod,
    const float* __restrict__ cw, const float* __restrict__ cb)
{
    int v = blockIdx.x, t = blockIdx.y;
    __shared__ float s_cw[96 * 32];
    __shared__ float s_cb[32], s_w[32], s_b[32];
    const float* cwp = cw + (size_t)(t * V + v) * 96 * 32;
    for (int i = threadIdx.x; i < 3072; i += 128) s_cw[i] = cwp[i];
    if (threadIdx.x < 32) {
        s_cb[threadIdx.x] = cb[(t * V + v) * 32 + threadIdx.x];
        s_w[threadIdx.x] = conv_w[threadIdx.x];
        s_b[threadIdx.x] = conv_b[threadIdx.x];
    }
    __syncthreads();
    int b = threadIdx.x;
    float yv = g_y[(b * T + t) * V + v];
    float rv = g_rsum[v];
    int nr = (int)inp[b * IN_B + 2 + v];
    int sw = (int)inp[b * IN_B + (1 + t) * IN_ROW + 0];
    int sd = (int)inp[b * IN_B + (1 + t) * IN_ROW + 1];
    const float* sp = sape + (nr * T + t) * E;
    const float* dwp = dow + (sw * V + v) * E;
    const float* tdp = tod + (sd * V + v) * E;

    float acc[32];
    #pragma unroll
    for (int e = 0; e < 32; e++) acc[e] = s_cb[e];

    #pragma unroll
    for (int f = 0; f < 32; f++) {
        float xf = yv * s_w[f] + rv * s_b[f];
        const float4* c4 = (const float4*)(s_cw + f * 32);
        #pragma unroll
        for (int e4 = 0; e4 < 8; e4++) {
            float4 w4 = c4[e4];
            acc[e4 * 4 + 0] += xf * w4.x; acc[e4 * 4 + 1] += xf * w4.y;
            acc[e4 * 4 + 2] += xf * w4.z; acc[e4 * 4 + 3] += xf * w4.w;
        }
    }
    #pragma unroll
    for (int f = 0; f < 32; f++) {
        float xf = sp[f];
        const float4* c4 = (const float4*)(s_cw + (32 + f) * 32);
        #pragma unroll
        for (int e4 = 0; e4 < 8; e4++) {
            float4 w4 = c4[e4];
            acc[e4 * 4 + 0] += xf * w4.x; acc[e4 * 4 + 1] += xf * w4.y;
            acc[e4 * 4 + 2] += xf * w4.z; acc[e4 * 4 + 3] += xf * w4.w;
        }
    }
    #pragma unroll
    for (int f = 0; f < 32; f++) {
        float xf = dwp[f] + tdp[f];
        const float4* c4 = (const float4*)(s_cw + (64 + f) * 32);
        #pragma unroll
        for (int e4 = 0; e4 < 8; e4++) {
            float4 w4 = c4[e4];
            acc[e4 * 4 + 0] += xf * w4.x; acc[e4 * 4 + 1] += xf * w4.y;
            acc[e4 * 4 + 2] += xf * w4.z; acc[e4 * 4 + 3] += xf * w4.w;
        }
    }
    // write bf16 hi/lo images: row (b*384+v), cols t*32..t*32+31
    union { unsigned short u[32]; uint4 q[4]; } ph, pl;
    #pragma unroll
    for (int e = 0; e < 32; e++) {
        float val = leakyf(acc[e]);
        bf16split(val, ph.u[e], pl.u[e]);
    }
    size_t o = ((size_t)b * 384 + v) * TE + t * E;
    uint4* dh = (uint4*)(g_Ahd + o);
    uint4* dl = (uint4*)(g_Ald + o);
    #pragma unroll
    for (int q = 0; q < 4; q++) { dh[q] = ph.q[q]; dl[q] = pl.q[q]; }
}

// ---------------- pad A-image rows V..383 with zeros -------------------------
__global__ void __launch_bounds__(256) k_padA() {
    int idx = blockIdx.x * 256 + threadIdx.x;   // B*77*48 uint4 tasks
    if (idx >= B * 77 * 48) return;
    int seg = idx % 48;
    int rem = idx / 48;
    int row = V + rem % 77;
    int b = rem / 77;
    size_t o = ((size_t)b * 384 + row) * TE + seg * 8;
    uint4 z = make_uint4(0, 0, 0, 0);
    *(uint4*)(g_Ahd + o) = z;
    *(uint4*)(g_Ald + o) = z;
}

// ---------------- pack: Wsum = W1[wk]+W2[dt], transposed to [n][k] -----------
__global__ void __launch_bounds__(256) k_packW(
    const float* __restrict__ inp,
    const float* __restrict__ w1all, const float* __restrict__ w2all)
{
    __shared__ float s[64 * 129];
    int nt = blockIdx.x, kc = blockIdx.y, b = blockIdx.z;
    int n0 = nt * 128, k0 = kc * 64;
    int wk = (int)inp[b * IN_B + 0];
    int dt = (int)inp[b * IN_B + 1];
    const float* w1p = w1all + (size_t)wk * TE * N2;
    const float* w2p = w2all + (size_t)dt * TE * N2;
    for (int idx = threadIdx.x; idx < 8192; idx += 256) {
        int k = idx >> 7, n = idx & 127;
        size_t g = (size_t)(k0 + k) * N2 + n0 + n;
        s[k * 129 + n] = w1p[g] + w2p[g];
    }
    __syncthreads();
    for (int t2 = threadIdx.x; t2 < 1024; t2 += 256) {
        int n = t2 >> 3, seg = t2 & 7;
        union { unsigned short u[8]; uint4 v; } ph, pl;
        #pragma unroll
        for (int j = 0; j < 8; j++) bf16split(s[(seg * 8 + j) * 129 + n], ph.u[j], pl.u[j]);
        size_t o = ((size_t)b * N2 + n0 + n) * TE + k0 + seg * 8;
        *(uint4*)(g_Whd + o) = ph.v;
        *(uint4*)(g_Wld + o) = pl.v;
    }
}

// ---------------- pack: tge2tg transpose -> [v 384][k 19648] hi/lo -----------
__global__ void __launch_bounds__(256) k_packT(const float* __restrict__ t2t) {
    __shared__ float s[64][65];
    int kc = blockIdx.x, nc = blockIdx.y;
    int k0 = kc * 64, n0 = nc * 64;
    for (int idx = threadIdx.x; idx < 4096; idx += 256) {
        int k = idx >> 6, n = idx & 63;
        s[k][n] = (n0 + n < V) ? t2t[(size_t)(k0 + k) * V + n0 + n] : 0.f;
    }
    __syncthreads();
    for (int t2 = threadIdx.x; t2 < 512; t2 += 256) {
        int n = t2 >> 3, seg = t2 & 7;
        union { unsigned short u[8]; uint4 v; } ph, pl;
        #pragma unroll
        for (int j = 0; j < 8; j++) bf16split(s[seg * 8 + j][n], ph.u[j], pl.u[j]);
        size_t o = (size_t)(n0 + n) * VE2 + k0 + seg * 8;
        *(uint4*)(g_Th + o) = ph.v;
        *(uint4*)(g_Tl + o) = pl.v;
    }
}

// ---------------- K3: dynamic layer via quad mma core ------------------------
__global__ void __launch_bounds__(256, 1) k_dyn_mma(
    const float* __restrict__ inp,
    const float* __restrict__ o1all, const float* __restrict__ o2all)
{
    extern __shared__ unsigned short qsm[];
    int nt = blockIdx.x, mt = blockIdx.y, b = blockIdx.z;
    int m0 = mt * 128, n0 = nt * 128;
    float acc[4][4][4];
    #pragma unroll
    for (int i = 0; i < 4; i++)
        #pragma unroll
        for (int j = 0; j < 4; j++)
            #pragma unroll
            for (int r = 0; r < 4; r++) acc[i][j][r] = 0.f;

    mma_gemm_quad(g_Ahd + (size_t)b * 384 * TE, g_Ald + (size_t)b * 384 * TE, TE,
                  g_Whd + (size_t)b * N2 * TE,  g_Wld + (size_t)b * N2 * TE,  TE,
                  m0, n0, 0, TE / 64, qsm, acc);

    int tid = threadIdx.x, lane = tid & 31, wid = tid >> 5;
    int wm = (wid & 1) * 64, wn = (wid >> 1) * 32;
    int gr = lane >> 2, tc = (lane & 3) * 2;
    int wk = (int)inp[b * IN_B + 0];
    int dt = (int)inp[b * IN_B + 1];
    const float* b1 = o1all + (size_t)wk * HB;
    const float* b2 = o2all + (size_t)dt * HB;
    float* hc = g_hC + (size_t)b * V * N2;
    #pragma unroll
    for (int mi = 0; mi < 4; mi++) {
        #pragma unroll
        for (int h = 0; h < 2; h++) {
            int g = m0 + wm + mi * 16 + gr + h * 8;
            if (g >= V) continue;
            #pragma unroll
            for (int ni = 0; ni < 4; ni++) {
                #pragma unroll
                for (int cb = 0; cb < 2; cb++) {
                    int n = n0 + wn + ni * 8 + tc + cb;
                    float val = 0.5f * (acc[mi][ni][h * 2 + cb] + b1[g * N2 + n] + b2[g * N2 + n]);
                    hc[(size_t)g * N2 + n] = leakyf(val);
                }
            }
        }
    }
}

// ---------------- K3b: transpose hC -> bf16 hi/lo h3 images ------------------
__global__ void __launch_bounds__(256) k_h3t() {
    __shared__ float s[8][768];
    int b = blockIdx.y, g0 = blockIdx.x * 8;
    for (int idx = threadIdx.x; idx < 8 * 768; idx += 256) {
        int r = idx / 768, n = idx % 768;
        int g = g0 + r;
        s[r][n] = (g < V) ? g_hC[(size_t)b * V * N2 + (size_t)g * N2 + n] : 0.f;
    }
    __syncthreads();
    for (int task = threadIdx.x; task < 12 * 8 * 16; task += 256) {
        int i4 = task & 15;
        int r = (task >> 4) & 7;
        int j = task >> 7;
        int g = g0 + r;
        if (g >= V) continue;
        union { unsigned short u[4]; uint2 w; } hh, ll;
        #pragma unroll
        for (int q = 0; q < 4; q++) {
            int i = i4 * 4 + q;
            bf16split(s[r][i * 12 + j], hh.u[q], ll.u[q]);
        }
        size_t o2 = (size_t)(b * 12 + j) * VE2 + (size_t)g * 64 + i4 * 4;
        *(uint2*)(g_h3h + o2) = hh.w;
        *(uint2*)(g_h3l + o2) = ll.w;
    }
}

// ---------------- K4: tg via quad mma core, split-K --------------------------
__global__ void __launch_bounds__(256, 1) k_tg_mma() {
    extern __shared__ unsigned short qsm[];
    int nt = blockIdx.x, mt = blockIdx.y, ks = blockIdx.z;
    int m0 = mt * 128, n0 = nt * 128;
    int c0 = (ks * 307) / KSPLIT, c1 = ((ks + 1) * 307) / KSPLIT;
    float acc[4][4][4];
    #pragma unroll
    for (int i = 0; i < 4; i++)
        #pragma unroll
        for (int j = 0; j < 4; j++)
            #pragma unroll
            for (int r = 0; r < 4; r++) acc[i][j][r] = 0.f;

    mma_gemm_quad(g_h3h, g_h3l, VE2, g_Th, g_Tl, VE2, m0, n0, c0 * 64, c1 - c0, qsm, acc);

    int tid = threadIdx.x, lane = tid & 31, wid = tid >> 5;
    int wm = (wid & 1) * 64, wn = (wid >> 1) * 32;
    int gr = lane >> 2, tc = (lane & 3) * 2;
    float* pp = g_tgp + (size_t)ks * BT * V;
    #pragma unroll
    for (int mi = 0; mi < 4; mi++) {
        #pragma unroll
        for (int h = 0; h < 2; h++) {
            int m = m0 + wm + mi * 16 + gr + h * 8;
            #pragma unroll
            for (int ni = 0; ni < 4; ni++) {
                #pragma unroll
                for (int cb = 0; cb < 2; cb++) {
                    int n = n0 + wn + ni * 8 + tc + cb;
                    if (n < V) pp[(size_t)m * V + n] = acc[mi][ni][h * 2 + cb];
                }
            }
        }
    }
}

// ---------------- K5: gt from bf16 h3 images --------------------------------
__global__ void k_gt(const float* __restrict__ g2g) {
    __shared__ float s[N2 * NPRE];
    for (int i = threadIdx.x; i < N2 * NPRE; i += 256) s[i] = g2g[i];
    __syncthreads();
    int wid = threadIdx.x >> 5, lane = threadIdx.x & 31;
    int r = blockIdx.x * 8 + wid;
    size_t base = (size_t)r * N2;   // flat [b][HB] view: row r = b*V+v
    float acc[NPRE] = {};
    for (int m = lane; m < N2; m += 32) {
        float a = bf16join(g_h3h[base + m], g_h3l[base + m]);
        const float* sm = s + m * NPRE;
        #pragma unroll
        for (int o = 0; o < NPRE; o++) acc[o] += a * sm[o];
    }
    #pragma unroll
    for (int o = 0; o < NPRE; o++) {
        #pragma unroll
        for (int st = 16; st > 0; st >>= 1)
            acc[o] += __shfl_xor_sync(0xffffffffu, acc[o], st);
    }
    if (lane == 0) {
        #pragma unroll
        for (int o = 0; o < NPRE; o++) g_gt[r * NPRE + o] = acc[o];
    }
}

// ---------------- K6: gates + weight1/2 + fully (tg split-K summed inline) --
__global__ void k_out(const float* __restrict__ w1, const float* __restrict__ w2,
                      const float* __restrict__ fw, const float* __restrict__ fb,
                      float* __restrict__ out)
{
    int idx = blockIdx.x * 256 + threadIdx.x;
    if (idx >= B * V) return;
    int b = idx / V, g = idx % V;
    float gt1[T], gt2[T];
    #pragma unroll
    for (int t = 0; t < T; t++) {
        float x3v = g_x3d[(b * T + t) * V + g];
        float tgv = 0.f;
        #pragma unroll
        for (int k = 0; k < KSPLIT; k++)
            tgv += g_tgp[(size_t)k * BT * V + (size_t)(b * T + t) * V + g];
        float gtv = g_gt[idx * NPRE + t];
        gt1[t] = (tgv + x3v) * (1.f / (1.f + expf(-tgv)));
        gt2[t] = (gtv + x3v) * (1.f / (1.f + expf(-gtv)));
    }
    float x1[NPRE], x2[NPRE];
    #pragma unroll
    for (int o = 0; o < NPRE; o++) { x1[o] = 0.f; x2[o] = 0.f; }
    #pragma unroll
    for (int i = 0; i < T; i++) {
        float a = gt1[i], c = gt2[i];
        #pragma unroll
        for (int o = 0; o < NPRE; o++) {
            x1[o] += w1[g * 144 + i * 12 + o] * a;
            x2[o] += w2[g * 144 + i * 12 + o] * c;
        }
    }
    #pragma unroll
    for (int o = 0; o < NPRE; o++) {
        float sacc = fb[o];
        #pragma unroll
        for (int i = 0; i < NPRE; i++) {
            sacc += x1[i] * fw[i * 12 + o] + x2[i] * fw[(12 + i) * 12 + o];
        }
        out[(size_t)b * NPRE * V + o * V + g] = sacc;
    }
}

// ---------------- launch -----------------------------------------------------
extern "C" void kernel_launch(void* const* d_in, const int* in_sizes, int n_in,
                              void* d_out, int out_size) {
    const float* inputs = (const float*)d_in[0];
    const int*   sdist  = (const int*)d_in[1];
    const float* conv_w = (const float*)d_in[2];
    const float* conv_b = (const float*)d_in[3];
    const float* srpe   = (const float*)d_in[4];
    const float* sape   = (const float*)d_in[5];
    const float* dow    = (const float*)d_in[6];
    const float* tod    = (const float*)d_in[7];
    const float* cw     = (const float*)d_in[8];
    const float* cb     = (const float*)d_in[9];
    const float* dw1    = (const float*)d_in[10];
    const float* do1    = (const float*)d_in[11];
    const float* dw2    = (const float*)d_in[12];
    const float* do2    = (const float*)d_in[13];
    const float* t2t    = (const float*)d_in[14];
    const float* g2g    = (const float*)d_in[15];
    const float* w1     = (const float*)d_in[16];
    const float* w2     = (const float*)d_in[17];
    const float* fw     = (const float*)d_in[18];
    const float* fb     = (const float*)d_in[19];
    float* out = (float*)d_out;

    cudaFuncSetAttribute(k_dyn_mma, cudaFuncAttributeMaxDynamicSharedMemorySize, QSMEM);
    cudaFuncSetAttribute(k_tg_mma, cudaFuncAttributeMaxDynamicSharedMemorySize, QSMEM);

    k_gather<<<(VV + 255) / 256, 256>>>(srpe, sdist);
    k_rel<<<V, 256>>>();
    k_x3<<<(BT * V + 255) / 256, 256>>>(inputs);
    k_packT<<<dim3(VE2 / 64, 6), 256>>>(t2t);
    k_packW<<<dim3(6, 6, B), 256>>>(inputs, dw1, dw2);
    k_padA<<<(B * 77 * 48 + 255) / 256, 256>>>();
    k_sgemm_y<<<dim3(5, 24), 256>>>();
    k_connect<<<dim3(V, T), 128>>>(inputs, conv_w, conv_b, sape, dow, tod, cw, cb);
    k_dyn_mma<<<dim3(6, 3, B), 256, QSMEM>>>(inputs, do1, do2);
    k_h3t<<<dim3(39, B), 256>>>();
    k_tg_mma<<<dim3(3, 12, KSPLIT), 256, QSMEM>>>();
    k_gt<<<(B * V) / 8, 256>>>(g2g);
    k_out<<<(B * V + 255) / 256, 256>>>(w1, w2, fw, fb, out);
}

// round 16
// speedup vs baseline: 3.0626x; 1.1472x over previous
#include <cuda_runtime.h>
#include <cuda_fp16.h>
#include <math.h>
#include <stdint.h>

#define V 307
#define T 12
#define E 32
#define B 128
#define NPRE 12
#define TE 384      // T*E
#define N2 768      // 2E*T
#define VE2 19648   // V*2E
#define VV 94249    // V*V
#define BT 1536     // B*T
#define IN_ROW 309
#define IN_B 4017   // 13*309
#define HB 235776   // V*N2 = 12*VE2
#define KSPLIT 4

#define MSTR 72         // smem row stride (fp16) = 144B, conflict-free ldmatrix
#define TILE_B 18432    // 128*MSTR*2 bytes per tile
#define STAGE_B 55296   // 3 tiles per stage {Ah, Al, Bh}
#define QSMEM 165888    // 3 stages

// ---------------- scratch ----------------------------------------------------
__device__ float g_rpe[VV];
__device__ float g_rpeT[VV];
__device__ float g_rel[VV];
__device__ float g_rsum[V];
__device__ float g_x3d[BT * V];
__device__ float g_y[BT * V];
__device__ float g_tgp[KSPLIT * BT * V];
__device__ float g_gt[B * V * NPRE];
// fp16 operand images
__device__ unsigned short g_Ahd[(size_t)B * 384 * TE];   // dyn A hi [b][row384][k384]
__device__ unsigned short g_Ald[(size_t)B * 384 * TE];   // dyn A lo
__device__ unsigned short g_Whd[(size_t)B * N2 * TE];    // dyn B' hi only (rounded)
__device__ unsigned short g_hCh[(size_t)B * V * N2];     // dyn out hi [b][g][n]
__device__ unsigned short g_hCl[(size_t)B * V * N2];     // dyn out lo
__device__ unsigned short g_h3h[(size_t)BT * VE2];       // tg A hi [bt][k] (= h3 flat)
__device__ unsigned short g_h3l[(size_t)BT * VE2];       // tg A lo
__device__ unsigned short g_Th[(size_t)384 * VE2];       // tg B' hi only (rounded)

__device__ __forceinline__ float leakyf(float x) { return x >= 0.f ? x : 0.3f * x; }

__device__ __forceinline__ uint32_t smem_u32(const void* p) {
    uint32_t a;
    asm("{ .reg .u64 t; cvta.to.shared.u64 t, %1; cvt.u32.u64 %0, t; }" : "=r"(a) : "l"(p));
    return a;
}
__device__ __forceinline__ void ldsm_x4(uint32_t& r0, uint32_t& r1, uint32_t& r2, uint32_t& r3, uint32_t addr) {
    asm volatile("ldmatrix.sync.aligned.m8n8.x4.shared.b16 {%0,%1,%2,%3}, [%4];"
        : "=r"(r0), "=r"(r1), "=r"(r2), "=r"(r3) : "r"(addr));
}
__device__ __forceinline__ void mma16816(float* c, const uint32_t* a, uint32_t b0, uint32_t b1) {
    asm volatile("mma.sync.aligned.m16n8k16.row.col.f32.f16.f16.f32 "
        "{%0,%1,%2,%3}, {%4,%5,%6,%7}, {%8,%9}, {%0,%1,%2,%3};"
        : "+f"(c[0]), "+f"(c[1]), "+f"(c[2]), "+f"(c[3])
        : "r"(a[0]), "r"(a[1]), "r"(a[2]), "r"(a[3]), "r"(b0), "r"(b1));
}
__device__ __forceinline__ void f16split(float x, unsigned short& hb, unsigned short& lb) {
    __half h = __float2half_rn(x);
    float r = x - __half2float(h);
    __half l = __float2half_rn(r);
    hb = *(unsigned short*)&h;
    lb = *(unsigned short*)&l;
}
__device__ __forceinline__ unsigned short f16rnd(float x) {
    __half h = __float2half_rn(x);
    return *(unsigned short*)&h;
}
__device__ __forceinline__ float f16join(unsigned short hb, unsigned short lb) {
    return __half2float(*(__half*)&hb) + __half2float(*(__half*)&lb);
}
__device__ __forceinline__ void cpasync16(uint32_t dst, const void* src) {
    asm volatile("cp.async.cg.shared.global [%0], [%1], 16;" :: "r"(dst), "l"(src));
}
#define CP_COMMIT() asm volatile("cp.async.commit_group;" ::: "memory")
#define CP_WAIT(n)  asm volatile("cp.async.wait_group %0;" :: "n"(n) : "memory")

// ---------------- tri mma core: 128x128 tile, BK=64, 3-stage, 2-pass fp16 ---
// C = (Ah+Al) * Bh ; A exact via hi/lo, B rounded to fp16.
__device__ __forceinline__ void mma_gemm_tri(
    const unsigned short* __restrict__ Ah, const unsigned short* __restrict__ Al, size_t lda,
    const unsigned short* __restrict__ Bh, size_t ldb,
    int m0, int n0, int kbeg, int nch,
    unsigned short* smem, float acc[4][4][4])
{
    int tid = threadIdx.x;
    int lane = tid & 31, wid = tid >> 5;
    int wm = (wid & 1) * 64, wn = (wid >> 1) * 32;
    int seg = tid & 7, rb = tid >> 3;
    uint32_t sbase = smem_u32(smem);

    auto issue = [&](int c) {
        uint32_t sb = sbase + (uint32_t)(c % 3) * STAGE_B;
        size_t k0 = (size_t)kbeg + (size_t)c * 64 + seg * 8;
        #pragma unroll
        for (int i = 0; i < 4; i++) {
            int r = rb + 32 * i;
            uint32_t so = (uint32_t)(r * MSTR + seg * 8) * 2;
            cpasync16(sb + so,              Ah + (size_t)(m0 + r) * lda + k0);
            cpasync16(sb + TILE_B + so,     Al + (size_t)(m0 + r) * lda + k0);
            cpasync16(sb + 2 * TILE_B + so, Bh + (size_t)(n0 + r) * ldb + k0);
        }
        CP_COMMIT();
    };

    issue(0);
    if (nch > 1) issue(1);
    for (int c = 0; c < nch; c++) {
        if (c + 2 <= nch) { CP_WAIT(1); } else { CP_WAIT(0); }
        __syncthreads();
        if (c + 2 < nch) issue(c + 2);
        uint32_t sb = sbase + (uint32_t)(c % 3) * STAGE_B;
        #pragma unroll
        for (int k16 = 0; k16 < 4; k16++) {
            uint32_t ah[4][4], al[4][4], bh[2][4];
            uint32_t acol = (uint32_t)(k16 * 16 + (lane >> 4) * 8) * 2;
            #pragma unroll
            for (int mi = 0; mi < 4; mi++) {
                uint32_t ao = sb + (uint32_t)(wm + mi * 16 + (lane & 15)) * (MSTR * 2) + acol;
                ldsm_x4(ah[mi][0], ah[mi][1], ah[mi][2], ah[mi][3], ao);
                ldsm_x4(al[mi][0], al[mi][1], al[mi][2], al[mi][3], ao + TILE_B);
            }
            uint32_t brow = (lane & 7) + (lane >> 4) * 8;
            uint32_t bcol = (uint32_t)(k16 * 16 + ((lane >> 3) & 1) * 8) * 2;
            #pragma unroll
            for (int nj = 0; nj < 2; nj++) {
                uint32_t bo = sb + (uint32_t)(wn + nj * 16 + brow) * (MSTR * 2) + bcol;
                ldsm_x4(bh[nj][0], bh[nj][1], bh[nj][2], bh[nj][3], bo + 2 * TILE_B);
            }
            #pragma unroll
            for (int mi = 0; mi < 4; mi++)
                #pragma unroll
                for (int ni = 0; ni < 4; ni++) {
                    uint32_t b0 = bh[ni >> 1][(ni & 1) * 2], b1 = bh[ni >> 1][(ni & 1) * 2 + 1];
                    mma16816(acc[mi][ni], ah[mi], b0, b1);
                    mma16816(acc[mi][ni], al[mi], b0, b1);
                }
        }
    }
    __syncthreads();
}

// ---------------- K0a: gather rpe + transpose -------------------------------
__global__ void k_gather(const float* __restrict__ srpe, const int* __restrict__ sdist) {
    int i = blockIdx.x * 256 + threadIdx.x;
    if (i < VV) {
        float v = srpe[sdist[i]];
        g_rpe[i] = v;
        g_rpeT[(i % V) * V + (i / V)] = v;
    }
}

// ---------------- K0b: rel = relu(rpe @ rpe^T), rowsum ----------------------
__global__ void k_rel() {
    __shared__ float s[V];
    __shared__ float red[256];
    int v = blockIdx.x;
    for (int k = threadIdx.x; k < V; k += 256) s[k] = g_rpe[v * V + k];
    __syncthreads();
    float lr = 0.f;
    for (int g = threadIdx.x; g < V; g += 256) {
        float sum = 0.f;
        for (int k = 0; k < V; k++) sum += s[k] * g_rpeT[k * V + g];
        float r = sum > 0.f ? sum : 0.f;
        g_rel[v * V + g] = r;
        lr += r;
    }
    red[threadIdx.x] = lr;
    __syncthreads();
    for (int st = 128; st > 0; st >>= 1) {
        if (threadIdx.x < st) red[threadIdx.x] += red[threadIdx.x + st];
        __syncthreads();
    }
    if (threadIdx.x == 0) g_rsum[v] = red[0];
}

// ---------------- K1x: extract dense x3 [bt][v] -----------------------------
__global__ void k_x3(const float* __restrict__ inp) {
    int idx = blockIdx.x * 256 + threadIdx.x;
    if (idx >= BT * V) return;
    int bt = idx / V, v = idx % V;
    int b = bt / T, t = bt % T;
    g_x3d[idx] = inp[b * IN_B + (1 + t) * IN_ROW + 2 + v];
}

// ---------------- small SGEMM tile core (64x64, BK=16) ----------------------
__device__ __forceinline__ void gemm_tile(
    const float* __restrict__ A, int lda, int M,
    const float* __restrict__ Bm, int ldb, int N,
    int m0, int n0, int kbeg, int kend, float acc[4][4])
{
    __shared__ float sA[16 * 64];
    __shared__ float sB[16 * 64];
    int tid = threadIdx.x;
    int tm = (tid >> 4) << 2;
    int tn = (tid & 15) << 2;
    for (int k0 = kbeg; k0 < kend; k0 += 16) {
        #pragma unroll
        for (int i = 0; i < 4; i++) {
            int idx = tid + i * 256;
            int m = idx >> 4;
            int kk = idx & 15;
            int gm = m0 + m, gk = k0 + kk;
            float v = (gm < M && gk < kend) ? A[(size_t)gm * lda + gk] : 0.f;
            sA[kk * 64 + m] = v;
        }
        #pragma unroll
        for (int i = 0; i < 4; i++) {
            int idx = tid + i * 256;
            int kk = idx >> 6;
            int n = idx & 63;
            int gk = k0 + kk, gn = n0 + n;
            float v = (gk < kend && gn < N) ? Bm[(size_t)gk * ldb + gn] : 0.f;
            sB[kk * 64 + n] = v;
        }
        __syncthreads();
        #pragma unroll
        for (int kk = 0; kk < 16; kk++) {
            float4 a4 = *(const float4*)(sA + kk * 64 + tm);
            float4 b4 = *(const float4*)(sB + kk * 64 + tn);
            float av[4] = {a4.x, a4.y, a4.z, a4.w};
            float bv[4] = {b4.x, b4.y, b4.z, b4.w};
            #pragma unroll
            for (int x = 0; x < 4; x++)
                #pragma unroll
                for (int y = 0; y < 4; y++)
                    acc[x][y] += av[x] * bv[y];
        }
        __syncthreads();
    }
}

// ---------------- K1: y = X3 (1536x307) @ rel (307x307) ---------------------
__global__ void k_sgemm_y() {
    float acc[4][4] = {};
    int m0 = blockIdx.y * 64, n0 = blockIdx.x * 64;
    gemm_tile(g_x3d, V, BT, g_rel, V, V, m0, n0, 0, V, acc);
    int tid = threadIdx.x;
    int tm = (tid >> 4) << 2, tn = (tid & 15) << 2;
    #pragma unroll
    for (int x = 0; x < 4; x++) {
        int m = m0 + tm + x;
        if (m >= BT) continue;
        #pragma unroll
        for (int y = 0; y < 4; y++) {
            int n = n0 + tn + y;
            if (n < V) g_y[m * V + n] = acc[x][y];
        }
    }
}

// ---------------- K2: connect layer; writes fp16 hi/lo A-images directly ----
__global__ void __launch_bounds__(128) k_connect(
    const float* __restrict__ inp,
    const float* __restrict__ conv_w, const float* __restrict__ conv_b,
    const float* __restrict__ sape, const float* __restrict__ dow,
    const float* __restrict__ tod,
    const float* __restrict__ cw, const float* __restrict__ cb)
{
    int v = blockIdx.x, t = blockIdx.y;
    __shared__ float s_cw[96 * 32];
    __shared__ float s_cb[32], s_w[32], s_b[32];
    const float* cwp = cw + (size_t)(t * V + v) * 96 * 32;
    for (int i = threadIdx.x; i < 3072; i += 128) s_cw[i] = cwp[i];
    if (threadIdx.x < 32) {
        s_cb[threadIdx.x] = cb[(t * V + v) * 32 + threadIdx.x];
        s_w[threadIdx.x] = conv_w[threadIdx.x];
        s_b[threadIdx.x] = conv_b[threadIdx.x];
    }
    __syncthreads();
    int b = threadIdx.x;
    float yv = g_y[(b * T + t) * V + v];
    float rv = g_rsum[v];
    int nr = (int)inp[b * IN_B + 2 + v];
    int sw = (int)inp[b * IN_B + (1 + t) * IN_ROW + 0];
    int sd = (int)inp[b * IN_B + (1 + t) * IN_ROW + 1];
    const float* sp = sape + (nr * T + t) * E;
    const float* dwp = dow + (sw * V + v) * E;
    const float* tdp = tod + (sd * V + v) * E;

    float acc[32];
    #pragma unroll
    for (int e = 0; e < 32; e++) acc[e] = s_cb[e];

    #pragma unroll
    for (int f = 0; f < 32; f++) {
        float xf = yv * s_w[f] + rv * s_b[f];
        const float4* c4 = (const float4*)(s_cw + f * 32);
        #pragma unroll
        for (int e4 = 0; e4 < 8; e4++) {
            float4 w4 = c4[e4];
            acc[e4 * 4 + 0] += xf * w4.x; acc[e4 * 4 + 1] += xf * w4.y;
            acc[e4 * 4 + 2] += xf * w4.z; acc[e4 * 4 + 3] += xf * w4.w;
        }
    }
    #pragma unroll
    for (int f = 0; f < 32; f++) {
        float xf = sp[f];
        const float4* c4 = (const float4*)(s_cw + (32 + f) * 32);
        #pragma unroll
        for (int e4 = 0; e4 < 8; e4++) {
            float4 w4 = c4[e4];
            acc[e4 * 4 + 0] += xf * w4.x; acc[e4 * 4 + 1] += xf * w4.y;
            acc[e4 * 4 + 2] += xf * w4.z; acc[e4 * 4 + 3] += xf * w4.w;
        }
    }
    #pragma unroll
    for (int f = 0; f < 32; f++) {
        float xf = dwp[f] + tdp[f];
        const float4* c4 = (const float4*)(s_cw + (64 + f) * 32);
        #pragma unroll
        for (int e4 = 0; e4 < 8; e4++) {
            float4 w4 = c4[e4];
            acc[e4 * 4 + 0] += xf * w4.x; acc[e4 * 4 + 1] += xf * w4.y;
            acc[e4 * 4 + 2] += xf * w4.z; acc[e4 * 4 + 3] += xf * w4.w;
        }
    }
    union { unsigned short u[32]; uint4 q[4]; } ph, pl;
    #pragma unroll
    for (int e = 0; e < 32; e++) {
        float val = leakyf(acc[e]);
        f16split(val, ph.u[e], pl.u[e]);
    }
    size_t o = ((size_t)b * 384 + v) * TE + t * E;
    uint4* dh = (uint4*)(g_Ahd + o);
    uint4* dl = (uint4*)(g_Ald + o);
    #pragma unroll
    for (int q = 0; q < 4; q++) { dh[q] = ph.q[q]; dl[q] = pl.q[q]; }
}

// ---------------- pad A-image rows V..383 with zeros -------------------------
__global__ void __launch_bounds__(256) k_padA() {
    int idx = blockIdx.x * 256 + threadIdx.x;
    if (idx >= B * 77 * 48) return;
    int seg = idx % 48;
    int rem = idx / 48;
    int row = V + rem % 77;
    int b = rem / 77;
    size_t o = ((size_t)b * 384 + row) * TE + seg * 8;
    uint4 z = make_uint4(0, 0, 0, 0);
    *(uint4*)(g_Ahd + o) = z;
    *(uint4*)(g_Ald + o) = z;
}

// ---------------- pack: Wsum = W1[wk]+W2[dt] -> fp16 [n][k] ------------------
__global__ void __launch_bounds__(256) k_packW(
    const float* __restrict__ inp,
    const float* __restrict__ w1all, const float* __restrict__ w2all)
{
    __shared__ float s[64 * 129];
    int nt = blockIdx.x, kc = blockIdx.y, b = blockIdx.z;
    int n0 = nt * 128, k0 = kc * 64;
    int wk = (int)inp[b * IN_B + 0];
    int dt = (int)inp[b * IN_B + 1];
    const float* w1p = w1all + (size_t)wk * TE * N2;
    const float* w2p = w2all + (size_t)dt * TE * N2;
    for (int idx = threadIdx.x; idx < 8192; idx += 256) {
        int k = idx >> 7, n = idx & 127;
        size_t g = (size_t)(k0 + k) * N2 + n0 + n;
        s[k * 129 + n] = w1p[g] + w2p[g];
    }
    __syncthreads();
    for (int t2 = threadIdx.x; t2 < 1024; t2 += 256) {
        int n = t2 >> 3, seg = t2 & 7;
        union { unsigned short u[8]; uint4 v; } ph;
        #pragma unroll
        for (int j = 0; j < 8; j++) ph.u[j] = f16rnd(s[(seg * 8 + j) * 129 + n]);
        size_t o = ((size_t)b * N2 + n0 + n) * TE + k0 + seg * 8;
        *(uint4*)(g_Whd + o) = ph.v;
    }
}

// ---------------- pack: tge2tg transpose -> fp16 [v 384][k 19648] ------------
__global__ void __launch_bounds__(256) k_packT(const float* __restrict__ t2t) {
    __shared__ float s[64][65];
    int kc = blockIdx.x, nc = blockIdx.y;
    int k0 = kc * 64, n0 = nc * 64;
    for (int idx = threadIdx.x; idx < 4096; idx += 256) {
        int k = idx >> 6, n = idx & 63;
        s[k][n] = (n0 + n < V) ? t2t[(size_t)(k0 + k) * V + n0 + n] : 0.f;
    }
    __syncthreads();
    for (int t2 = threadIdx.x; t2 < 512; t2 += 256) {
        int n = t2 >> 3, seg = t2 & 7;
        union { unsigned short u[8]; uint4 v; } ph;
        #pragma unroll
        for (int j = 0; j < 8; j++) ph.u[j] = f16rnd(s[seg * 8 + j][n]);
        size_t o = (size_t)(n0 + n) * VE2 + k0 + seg * 8;
        *(uint4*)(g_Th + o) = ph.v;
    }
}

// ---------------- K3: dynamic layer via tri mma core -------------------------
__global__ void __launch_bounds__(256, 1) k_dyn_mma(
    const float* __restrict__ inp,
    const float* __restrict__ o1all, const float* __restrict__ o2all)
{
    extern __shared__ unsigned short qsm[];
    int nt = blockIdx.x, mt = blockIdx.y, b = blockIdx.z;
    int m0 = mt * 128, n0 = nt * 128;
    float acc[4][4][4];
    #pragma unroll
    for (int i = 0; i < 4; i++)
        #pragma unroll
        for (int j = 0; j < 4; j++)
            #pragma unroll
            for (int r = 0; r < 4; r++) acc[i][j][r] = 0.f;

    mma_gemm_tri(g_Ahd + (size_t)b * 384 * TE, g_Ald + (size_t)b * 384 * TE, TE,
                 g_Whd + (size_t)b * N2 * TE, TE,
                 m0, n0, 0, TE / 64, qsm, acc);

    int tid = threadIdx.x, lane = tid & 31, wid = tid >> 5;
    int wm = (wid & 1) * 64, wn = (wid >> 1) * 32;
    int gr = lane >> 2, tc = (lane & 3) * 2;
    int wk = (int)inp[b * IN_B + 0];
    int dt = (int)inp[b * IN_B + 1];
    const float* b1 = o1all + (size_t)wk * HB;
    const float* b2 = o2all + (size_t)dt * HB;
    #pragma unroll
    for (int mi = 0; mi < 4; mi++) {
        #pragma unroll
        for (int h = 0; h < 2; h++) {
            int g = m0 + wm + mi * 16 + gr + h * 8;
            if (g >= V) continue;
            #pragma unroll
            for (int ni = 0; ni < 4; ni++) {
                int n = n0 + wn + ni * 8 + tc;   // even, two consecutive values
                float v0 = 0.5f * (acc[mi][ni][h * 2 + 0] + b1[g * N2 + n] + b2[g * N2 + n]);
                float v1 = 0.5f * (acc[mi][ni][h * 2 + 1] + b1[g * N2 + n + 1] + b2[g * N2 + n + 1]);
                v0 = leakyf(v0); v1 = leakyf(v1);
                union { unsigned short u[2]; uint32_t w; } hh, ll;
                f16split(v0, hh.u[0], ll.u[0]);
                f16split(v1, hh.u[1], ll.u[1]);
                size_t o = (size_t)b * V * N2 + (size_t)g * N2 + n;
                *(uint32_t*)(g_hCh + o) = hh.w;
                *(uint32_t*)(g_hCl + o) = ll.w;
            }
        }
    }
}

// ---------------- K3b: transpose hC -> fp16 hi/lo h3 images ------------------
__global__ void __launch_bounds__(256) k_h3t() {
    __shared__ float s[8][768];
    int b = blockIdx.y, g0 = blockIdx.x * 8;
    for (int idx = threadIdx.x; idx < 8 * 384; idx += 256) {
        int r = idx / 384, n2 = idx % 384;
        int g = g0 + r;
        float v0 = 0.f, v1 = 0.f;
        if (g < V) {
            size_t o = (size_t)b * V * N2 + (size_t)g * N2 + n2 * 2;
            union { uint32_t w; unsigned short u[2]; } ch, cl;
            ch.w = *(const uint32_t*)(g_hCh + o);
            cl.w = *(const uint32_t*)(g_hCl + o);
            v0 = f16join(ch.u[0], cl.u[0]);
            v1 = f16join(ch.u[1], cl.u[1]);
        }
        s[r][n2 * 2] = v0;
        s[r][n2 * 2 + 1] = v1;
    }
    __syncthreads();
    for (int task = threadIdx.x; task < 12 * 8 * 16; task += 256) {
        int i4 = task & 15;
        int r = (task >> 4) & 7;
        int j = task >> 7;
        int g = g0 + r;
        if (g >= V) continue;
        union { unsigned short u[4]; uint2 w; } hh, ll;
        #pragma unroll
        for (int q = 0; q < 4; q++) {
            int i = i4 * 4 + q;
            f16split(s[r][i * 12 + j], hh.u[q], ll.u[q]);
        }
        size_t o2 = (size_t)(b * 12 + j) * VE2 + (size_t)g * 64 + i4 * 4;
        *(uint2*)(g_h3h + o2) = hh.w;
        *(uint2*)(g_h3l + o2) = ll.w;
    }
}

// ---------------- K4: tg via tri mma core, split-K ---------------------------
__global__ void __launch_bounds__(256, 1) k_tg_mma() {
    extern __shared__ unsigned short qsm[];
    int nt = blockIdx.x, mt = blockIdx.y, ks = blockIdx.z;
    int m0 = mt * 128, n0 = nt * 128;
    int c0 = (ks * 307) / KSPLIT, c1 = ((ks + 1) * 307) / KSPLIT;
    float acc[4][4][4];
    #pragma unroll
    for (int i = 0; i < 4; i++)
        #pragma unroll
        for (int j = 0; j < 4; j++)
            #pragma unroll
            for (int r = 0; r < 4; r++) acc[i][j][r] = 0.f;

    mma_gemm_tri(g_h3h, g_h3l, VE2, g_Th, VE2, m0, n0, c0 * 64, c1 - c0, qsm, acc);

    int tid = threadIdx.x, lane = tid & 31, wid = tid >> 5;
    int wm = (wid & 1) * 64, wn = (wid >> 1) * 32;
    int gr = lane >> 2, tc = (lane & 3) * 2;
    float* pp = g_tgp + (size_t)ks * BT * V;
    #pragma unroll
    for (int mi = 0; mi < 4; mi++) {
        #pragma unroll
        for (int h = 0; h < 2; h++) {
            int m = m0 + wm + mi * 16 + gr + h * 8;
            #pragma unroll
            for (int ni = 0; ni < 4; ni++) {
                #pragma unroll
                for (int cb = 0; cb < 2; cb++) {
                    int n = n0 + wn + ni * 8 + tc + cb;
                    if (n < V) pp[(size_t)m * V + n] = acc[mi][ni][h * 2 + cb];
                }
            }
        }
    }
}

// ---------------- K5: gt from fp16 h3 images --------------------------------
__global__ void k_gt(const float* __restrict__ g2g) {
    __shared__ float s[N2 * NPRE];
    for (int i = threadIdx.x; i < N2 * NPRE; i += 256) s[i] = g2g[i];
    __syncthreads();
    int wid = threadIdx.x >> 5, lane = threadIdx.x & 31;
    int r = blockIdx.x * 8 + wid;
    size_t base = (size_t)r * N2;   // flat reshape view (matches reference)
    float acc[NPRE] = {};
    for (int m = lane; m < N2; m += 32) {
        float a = f16join(g_h3h[base + m], g_h3l[base + m]);
        const float* sm = s + m * NPRE;
        #pragma unroll
        for (int o = 0; o < NPRE; o++) acc[o] += a * sm[o];
    }
    #pragma unroll
    for (int o = 0; o < NPRE; o++) {
        #pragma unroll
        for (int st = 16; st > 0; st >>= 1)
            acc[o] += __shfl_xor_sync(0xffffffffu, acc[o], st);
    }
    if (lane == 0) {
        #pragma unroll
        for (int o = 0; o < NPRE; o++) g_gt[r * NPRE + o] = acc[o];
    }
}

// ---------------- K6: gates + weight1/2 + fully (tg split-K summed inline) --
__global__ void k_out(const float* __restrict__ w1, const float* __restrict__ w2,
                      const float* __restrict__ fw, const float* __restrict__ fb,
                      float* __restrict__ out)
{
    int idx = blockIdx.x * 256 + threadIdx.x;
    if (idx >= B * V) return;
    int b = idx / V, g = idx % V;
    float gt1[T], gt2[T];
    #pragma unroll
    for (int t = 0; t < T; t++) {
        float x3v = g_x3d[(b * T + t) * V + g];
        float tgv = 0.f;
        #pragma unroll
        for (int k = 0; k < KSPLIT; k++)
            tgv += g_tgp[(size_t)k * BT * V + (size_t)(b * T + t) * V + g];
        float gtv = g_gt[idx * NPRE + t];
        gt1[t] = (tgv + x3v) * (1.f / (1.f + expf(-tgv)));
        gt2[t] = (gtv + x3v) * (1.f / (1.f + expf(-gtv)));
    }
    float x1[NPRE], x2[NPRE];
    #pragma unroll
    for (int o = 0; o < NPRE; o++) { x1[o] = 0.f; x2[o] = 0.f; }
    #pragma unroll
    for (int i = 0; i < T; i++) {
        float a = gt1[i], c = gt2[i];
        #pragma unroll
        for (int o = 0; o < NPRE; o++) {
            x1[o] += w1[g * 144 + i * 12 + o] * a;
            x2[o] += w2[g * 144 + i * 12 + o] * c;
        }
    }
    #pragma unroll
    for (int o = 0; o < NPRE; o++) {
        float sacc = fb[o];
        #pragma unroll
        for (int i = 0; i < NPRE; i++) {
            sacc += x1[i] * fw[i * 12 + o] + x2[i] * fw[(12 + i) * 12 + o];
        }
        out[(size_t)b * NPRE * V + o * V + g] = sacc;
    }
}

// ---------------- launch -----------------------------------------------------
extern "C" void kernel_launch(void* const* d_in, const int* in_sizes, int n_in,
                              void* d_out, int out_size) {
    const float* inputs = (const float*)d_in[0];
    const int*   sdist  = (const int*)d_in[1];
    const float* conv_w = (const float*)d_in[2];
    const float* conv_b = (const float*)d_in[3];
    const float* srpe   = (const float*)d_in[4];
    const float* sape   = (const float*)d_in[5];
    const float* dow    = (const float*)d_in[6];
    const float* tod    = (const float*)d_in[7];
    const float* cw     = (const float*)d_in[8];
    const float* cb     = (const float*)d_in[9];
    const float* dw1    = (const float*)d_in[10];
    const float* do1    = (const float*)d_in[11];
    const float* dw2    = (const float*)d_in[12];
    const float* do2    = (const float*)d_in[13];
    const float* t2t    = (const float*)d_in[14];
    const float* g2g    = (const float*)d_in[15];
    const float* w1     = (const float*)d_in[16];
    const float* w2     = (const float*)d_in[17];
    const float* fw     = (const float*)d_in[18];
    const float* fb     = (const float*)d_in[19];
    float* out = (float*)d_out;

    cudaFuncSetAttribute(k_dyn_mma, cudaFuncAttributeMaxDynamicSharedMemorySize, QSMEM);
    cudaFuncSetAttribute(k_tg_mma, cudaFuncAttributeMaxDynamicSharedMemorySize, QSMEM);

    k_gather<<<(VV + 255) / 256, 256>>>(srpe, sdist);
    k_rel<<<V, 256>>>();
    k_x3<<<(BT * V + 255) / 256, 256>>>(inputs);
    k_packT<<<dim3(VE2 / 64, 6), 256>>>(t2t);
    k_packW<<<dim3(6, 6, B), 256>>>(inputs, dw1, dw2);
    k_padA<<<(B * 77 * 48 + 255) / 256, 256>>>();
    k_sgemm_y<<<dim3(5, 24), 256>>>();
    k_connect<<<dim3(V, T), 128>>>(inputs, conv_w, conv_b, sape, dow, tod, cw, cb);
    k_dyn_mma<<<dim3(6, 3, B), 256, QSMEM>>>(inputs, do1, do2);
    k_h3t<<<dim3(39, B), 256>>>();
    k_tg_mma<<<dim3(3, 12, KSPLIT), 256, QSMEM>>>();
    k_gt<<<(B * V) / 8, 256>>>(g2g);
    k_out<<<(B * V + 255) / 256, 256>>>(w1, w2, fw, fb, out);
}